// round 2
// baseline (speedup 1.0000x reference)
#include <cuda_runtime.h>
#include <math_constants.h>

#define H_IMG 256
#define W_IMG 256
#define A_ANG 64
#define DC_DET 1024
#define NSAMP 512
#define NPAD 2048
#define FEAT 32
#define NPIX (H_IMG * W_IMG)

// ---------------- scratch (device globals: allocation-free) ----------------
// NOTE: these are only ever referenced from DEVICE code (passing a __device__
// symbol as a kernel argument from host code yields the host shadow address —
// that was the round-1 bug).
__device__ float g_sino[A_ANG * DC_DET];
__device__ float g_h[NPAD];
__device__ float g_filt[A_ANG * DC_DET];
__device__ float g_xinput[NPIX];
__device__ float g_feat1[FEAT * NPIX];
__device__ float g_xforward[FEAT * NPIX];
__device__ float g_hs[FEAT * NPIX];
__device__ float g_t1[FEAT * NPIX];
__device__ float g_t2[FEAT * NPIX];

// ---------------- fan-beam forward projection ----------------
__device__ __forceinline__ float img_tap(const float* __restrict__ img, int xi, int yi) {
    if ((unsigned)xi < (unsigned)W_IMG && (unsigned)yi < (unsigned)H_IMG)
        return __ldg(&img[yi * W_IMG + xi]);
    return 0.0f;
}

__global__ void k_fanfwd(const float* __restrict__ img, const float* __restrict__ theta) {
    int gid = blockIdx.x * blockDim.x + threadIdx.x;
    int a = gid >> 10;
    int dc = gid & 1023;
    float th = theta[a];
    float c = cosf(th), s = sinf(th);
    float srcx = 500.0f * c, srcy = 500.0f * s;
    float u = ((float)dc - 511.5f) * 2.0f;
    float dx = -1000.0f * c - u * s;
    float dy = -1000.0f * s + u * c;
    float L = sqrtf(dx * dx + dy * dy);

    // clip t in (0,1) against the padded image box (taps can be nonzero only
    // for |px|,|py| < 128.5)
    const float lo = -128.51f, hi = 128.51f;
    float tlo = 0.0f, thi = 1.0f;
    {
        if (fabsf(dx) > 1e-9f) {
            float ta = (lo - srcx) / dx, tb = (hi - srcx) / dx;
            tlo = fmaxf(tlo, fminf(ta, tb));
            thi = fminf(thi, fmaxf(ta, tb));
        } else if (srcx < lo || srcx > hi) { thi = -1.0f; }
        if (fabsf(dy) > 1e-9f) {
            float ta = (lo - srcy) / dy, tb = (hi - srcy) / dy;
            tlo = fmaxf(tlo, fminf(ta, tb));
            thi = fminf(thi, fmaxf(ta, tb));
        } else if (srcy < lo || srcy > hi) { thi = -1.0f; }
    }
    float acc = 0.0f;
    if (thi > tlo) {
        int kmin = (int)ceilf(tlo * (float)NSAMP - 0.5f) - 1;
        int kmax = (int)floorf(thi * (float)NSAMP - 0.5f) + 1;
        kmin = max(kmin, 0);
        kmax = min(kmax, NSAMP - 1);
        for (int k = kmin; k <= kmax; ++k) {
            float t = ((float)k + 0.5f) * (1.0f / (float)NSAMP);
            float px = fmaf(t, dx, srcx);
            float py = fmaf(t, dy, srcy);
            float cx = px + 127.5f, cy = py + 127.5f;
            float x0 = floorf(cx), y0 = floorf(cy);
            float fx = cx - x0, fy = cy - y0;
            int xi = (int)x0, yi = (int)y0;
            float v00 = img_tap(img, xi, yi);
            float v01 = img_tap(img, xi + 1, yi);
            float v10 = img_tap(img, xi, yi + 1);
            float v11 = img_tap(img, xi + 1, yi + 1);
            float vx0 = fmaf(fx, v01 - v00, v00);
            float vx1 = fmaf(fx, v11 - v10, v10);
            acc += fmaf(fy, vx1 - vx0, vx0);
        }
    }
    g_sino[gid] = acc * (L * (1.0f / (float)NSAMP));
}

// ---------------- Ram-Lak impulse response ----------------
// h = irfft(2*rfftfreq(2048)):
//   h[j] = (1/2048) * [ (1/512) * sum_{k=1}^{1023} k*cos(pi*k*j/1024) + (-1)^j ]
__global__ void k_ramp() {
    int j = blockIdx.x;
    double part = 0.0;
    for (int k = 1 + threadIdx.x; k < 1024; k += 128) {
        int p = (k * j) & 2047;
        int r = (p > 1024) ? (2048 - p) : p;
        float sg = 1.0f;
        if (r > 512) { r = 1024 - r; sg = -1.0f; }
        float cv = sg * cosf((float)r * (float)(CUDART_PI / 1024.0));
        part += (double)((float)k * cv);
    }
    __shared__ double red[128];
    red[threadIdx.x] = part;
    __syncthreads();
    for (int s2 = 64; s2 > 0; s2 >>= 1) {
        if (threadIdx.x < s2) red[threadIdx.x] += red[threadIdx.x + s2];
        __syncthreads();
    }
    if (threadIdx.x == 0) {
        double v = red[0] * (1.0 / 512.0) + ((j & 1) ? -1.0 : 1.0);
        g_h[j] = (float)(v * (1.0 / 2048.0));
    }
}

// ---------------- ramp filtering (circular conv with zero-pad) - sinogram ----
__global__ void k_filter(const float* __restrict__ obs) {
    __shared__ float xs[DC_DET];
    __shared__ float hs[NPAD];
    int a = blockIdx.x >> 2;
    int seg = blockIdx.x & 3;
    for (int i = threadIdx.x; i < DC_DET; i += 256) xs[i] = g_sino[a * DC_DET + i];
    for (int i = threadIdx.x; i < NPAD; i += 256) hs[i] = g_h[i];
    __syncthreads();
    int n = seg * 256 + threadIdx.x;
    float acc = 0.0f;
#pragma unroll 8
    for (int m = 0; m < DC_DET; ++m)
        acc = fmaf(xs[m], hs[(n - m) & (NPAD - 1)], acc);
    g_filt[a * DC_DET + n] = acc - obs[a * DC_DET + n];
}

// ---------------- pixel-driven fan-beam backprojection + x_input ----------------
__global__ void k_backproj(const float* __restrict__ theta, const float* __restrict__ x_in,
                           const float* __restrict__ lam_p) {
    __shared__ float cs[A_ANG], ss[A_ANG];
    int tid = threadIdx.x;
    if (tid < A_ANG) {
        float th = theta[tid];
        cs[tid] = cosf(th);
        ss[tid] = sinf(th);
    }
    __syncthreads();
    int pix = blockIdx.x * 256 + tid;
    int py = pix >> 8, px = pix & 255;
    float gx = (float)px - 127.5f;
    float gy = (float)py - 127.5f;
    float acc = 0.0f;
    for (int a = 0; a < A_ANG; ++a) {
        float c = cs[a], s = ss[a];
        float xr = gx * c + gy * s;
        float yr = -gx * s + gy * c;
        float invd = __fdividef(1.0f, 500.0f - xr);
        float uu = yr * 1000.0f * invd;
        float wgt = 250000.0f * invd * invd;
        float iu = uu * 0.5f + 511.5f;
        float i0f = floorf(iu);
        float fr = iu - i0f;
        int i0 = (int)i0f;
        const float* row = g_filt + a * DC_DET;
        float v0 = ((unsigned)i0 < (unsigned)DC_DET) ? __ldg(&row[i0]) : 0.0f;
        float v1 = ((unsigned)(i0 + 1) < (unsigned)DC_DET) ? __ldg(&row[i0 + 1]) : 0.0f;
        acc = fmaf(wgt, fmaf(fr, v1 - v0, v0), acc);
    }
    float lam = __ldg(lam_p);
    g_xinput[pix] = x_in[pix] - lam * acc * (float)(CUDART_PI / 64.0);
}

// ---------------- conv 1->32 (3x3, SAME) + relu : g_xinput -> g_feat1 --------
__global__ void k_conv1f(const float* __restrict__ w) {
    __shared__ float ws[9][32];
    int tid = threadIdx.x;
    for (int i = tid; i < 288; i += 256) {
        int k = i >> 5, oc = i & 31;
        ws[k][oc] = w[oc * 9 + k];
    }
    __syncthreads();
    int pix = blockIdx.x * 256 + tid;
    int py = pix >> 8, px = pix & 255;
    float pv[9];
#pragma unroll
    for (int dy = 0; dy < 3; ++dy)
#pragma unroll
        for (int dxk = 0; dxk < 3; ++dxk) {
            int yy = py - 1 + dy, xx = px - 1 + dxk;
            pv[dy * 3 + dxk] = ((unsigned)yy < (unsigned)H_IMG && (unsigned)xx < (unsigned)W_IMG)
                                   ? __ldg(&g_xinput[yy * W_IMG + xx]) : 0.0f;
        }
    float acc[32];
#pragma unroll
    for (int o = 0; o < 32; ++o) acc[o] = 0.0f;
#pragma unroll
    for (int k = 0; k < 9; ++k) {
#pragma unroll
        for (int o4 = 0; o4 < 8; ++o4) {
            float4 wv = *(const float4*)&ws[k][o4 * 4];
            acc[o4 * 4 + 0] = fmaf(pv[k], wv.x, acc[o4 * 4 + 0]);
            acc[o4 * 4 + 1] = fmaf(pv[k], wv.y, acc[o4 * 4 + 1]);
            acc[o4 * 4 + 2] = fmaf(pv[k], wv.z, acc[o4 * 4 + 2]);
            acc[o4 * 4 + 3] = fmaf(pv[k], wv.w, acc[o4 * 4 + 3]);
        }
    }
#pragma unroll
    for (int o = 0; o < 32; ++o)
        g_feat1[o * NPIX + pix] = fmaxf(acc[o], 0.0f);
}

// ---------------- conv 32->32 (3x3, SAME), tiled, FMA-bound ----------------
// VARIANT 0: g_feat1    -> g_xforward (plain) + g_hs (soft-threshold)
// VARIANT 1: g_hs       -> g_t1 (relu)
// VARIANT 2: g_xforward -> g_t2 (relu)
template <int VARIANT>
__global__ void __launch_bounds__(128) k_conv32(const float* __restrict__ w,
                                                const float* __restrict__ thr_p) {
    const float* __restrict__ in =
        (VARIANT == 0) ? g_feat1 : ((VARIANT == 1) ? g_hs : g_xforward);
    float* __restrict__ out =
        (VARIANT == 0) ? g_xforward : ((VARIANT == 1) ? g_t1 : g_t2);

    __shared__ float ws[32][9][32];    // [ic][tap][oc]
    __shared__ float ins[8][18][18];   // 8-ic chunk of the 16x16 tile + halo
    int tid = threadIdx.x;
    for (int i = tid; i < 32 * 9 * 32; i += 128) {
        int oc = i / 288;
        int r = i - oc * 288;
        int ic = r / 9;
        int k = r - ic * 9;
        ws[ic][k][oc] = w[i];
    }
    int bx = blockIdx.x & 15, by = blockIdx.x >> 4;
    int tx0 = bx * 16, ty0 = by * 16;
    int lx = tid & 15, ly = tid >> 4;  // ly in [0,8)

    float acc0[32], acc1[32];
#pragma unroll
    for (int o = 0; o < 32; ++o) { acc0[o] = 0.0f; acc1[o] = 0.0f; }

    for (int cc = 0; cc < 4; ++cc) {
        __syncthreads();
        for (int i = tid; i < 8 * 18 * 18; i += 128) {
            int icc = i / 324;
            int rr = (i - icc * 324) / 18;
            int c2 = i - icc * 324 - rr * 18;
            int gy = ty0 - 1 + rr, gx2 = tx0 - 1 + c2;
            float v = 0.0f;
            if ((unsigned)gy < (unsigned)H_IMG && (unsigned)gx2 < (unsigned)W_IMG)
                v = in[(cc * 8 + icc) * NPIX + gy * W_IMG + gx2];
            ins[icc][rr][c2] = v;
        }
        __syncthreads();
#pragma unroll
        for (int icc = 0; icc < 8; ++icc) {
            int ic = cc * 8 + icc;
            float p0[9], p1[9];
#pragma unroll
            for (int dy = 0; dy < 3; ++dy)
#pragma unroll
                for (int dxk = 0; dxk < 3; ++dxk) {
                    p0[dy * 3 + dxk] = ins[icc][ly + dy][lx + dxk];
                    p1[dy * 3 + dxk] = ins[icc][ly + 8 + dy][lx + dxk];
                }
#pragma unroll
            for (int k = 0; k < 9; ++k) {
#pragma unroll
                for (int o4 = 0; o4 < 8; ++o4) {
                    float4 wv = *(const float4*)&ws[ic][k][o4 * 4];
                    acc0[o4 * 4 + 0] = fmaf(p0[k], wv.x, acc0[o4 * 4 + 0]);
                    acc0[o4 * 4 + 1] = fmaf(p0[k], wv.y, acc0[o4 * 4 + 1]);
                    acc0[o4 * 4 + 2] = fmaf(p0[k], wv.z, acc0[o4 * 4 + 2]);
                    acc0[o4 * 4 + 3] = fmaf(p0[k], wv.w, acc0[o4 * 4 + 3]);
                    acc1[o4 * 4 + 0] = fmaf(p1[k], wv.x, acc1[o4 * 4 + 0]);
                    acc1[o4 * 4 + 1] = fmaf(p1[k], wv.y, acc1[o4 * 4 + 1]);
                    acc1[o4 * 4 + 2] = fmaf(p1[k], wv.z, acc1[o4 * 4 + 2]);
                    acc1[o4 * 4 + 3] = fmaf(p1[k], wv.w, acc1[o4 * 4 + 3]);
                }
            }
        }
    }
    int x = tx0 + lx;
    int yA = ty0 + ly, yB = yA + 8;
    float thr = (VARIANT == 0) ? __ldg(thr_p) : 0.0f;
#pragma unroll
    for (int o = 0; o < 32; ++o) {
        float v0 = acc0[o], v1 = acc1[o];
        if (VARIANT != 0) { v0 = fmaxf(v0, 0.0f); v1 = fmaxf(v1, 0.0f); }
        out[o * NPIX + yA * W_IMG + x] = v0;
        out[o * NPIX + yB * W_IMG + x] = v1;
        if (VARIANT == 0) {
            float m0 = fmaxf(fabsf(v0) - thr, 0.0f);
            float m1 = fmaxf(fabsf(v1) - thr, 0.0f);
            g_hs[o * NPIX + yA * W_IMG + x] = (v0 > 0.0f) ? m0 : ((v0 < 0.0f) ? -m0 : 0.0f);
            g_hs[o * NPIX + yB * W_IMG + x] = (v1 > 0.0f) ? m1 : ((v1 < 0.0f) ? -m1 : 0.0f);
        }
    }
}

// ---------------- conv 32->1 (3x3, SAME), optional subtract (symloss) --------
// SUB 0: in = g_t1, out = x_pred      SUB 1: in = g_t2, out = x_est - x_input
template <int SUB>
__global__ void k_conv32to1(const float* __restrict__ w, float* __restrict__ out) {
    const float* __restrict__ in = SUB ? g_t2 : g_t1;
    __shared__ float ws[288];
    __shared__ float ins[8][18][18];
    int tid = threadIdx.x;  // 256 threads, 16x16 tile
    for (int i = tid; i < 288; i += 256) ws[i] = w[i];  // (1,32,3,3): w[ic*9+k]
    int bx = blockIdx.x & 15, by = blockIdx.x >> 4;
    int tx0 = bx * 16, ty0 = by * 16;
    int lx = tid & 15, ly = tid >> 4;  // ly in [0,16)
    float acc = 0.0f;
    for (int cc = 0; cc < 4; ++cc) {
        __syncthreads();
        for (int i = tid; i < 8 * 18 * 18; i += 256) {
            int icc = i / 324;
            int rr = (i - icc * 324) / 18;
            int c2 = i - icc * 324 - rr * 18;
            int gy = ty0 - 1 + rr, gx2 = tx0 - 1 + c2;
            float v = 0.0f;
            if ((unsigned)gy < (unsigned)H_IMG && (unsigned)gx2 < (unsigned)W_IMG)
                v = in[(cc * 8 + icc) * NPIX + gy * W_IMG + gx2];
            ins[icc][rr][c2] = v;
        }
        __syncthreads();
#pragma unroll
        for (int icc = 0; icc < 8; ++icc) {
            int ic = cc * 8 + icc;
#pragma unroll
            for (int dy = 0; dy < 3; ++dy)
#pragma unroll
                for (int dxk = 0; dxk < 3; ++dxk)
                    acc = fmaf(ins[icc][ly + dy][lx + dxk], ws[ic * 9 + dy * 3 + dxk], acc);
        }
    }
    int pix = (ty0 + ly) * W_IMG + tx0 + lx;
    out[pix] = SUB ? (acc - g_xinput[pix]) : acc;
}

// ---------------- launch ----------------
extern "C" void kernel_launch(void* const* d_in, const int* in_sizes, int n_in,
                              void* d_out, int out_size) {
    const float* x        = (const float*)d_in[0];
    const float* theta    = (const float*)d_in[1];
    const float* sinogram = (const float*)d_in[2];
    const float* lam      = (const float*)d_in[3];
    const float* thr      = (const float*)d_in[4];
    const float* w1f      = (const float*)d_in[5];
    const float* w2f      = (const float*)d_in[6];
    const float* w1b      = (const float*)d_in[7];
    const float* w2b      = (const float*)d_in[8];
    float* out = (float*)d_out;  // [0:65536) x_pred, [65536:131072) symloss

    k_fanfwd<<<256, 256>>>(x, theta);
    k_ramp<<<NPAD, 128>>>();
    k_filter<<<A_ANG * 4, 256>>>(sinogram);
    k_backproj<<<256, 256>>>(theta, x, lam);
    k_conv1f<<<256, 256>>>(w1f);
    k_conv32<0><<<256, 128>>>(w2f, thr);
    k_conv32<1><<<256, 128>>>(w1b, nullptr);
    k_conv32<2><<<256, 128>>>(w1b, nullptr);
    k_conv32to1<0><<<256, 256>>>(w2b, out);
    k_conv32to1<1><<<256, 256>>>(w2b, out + NPIX);
}

// round 3
// speedup vs baseline: 1.9183x; 1.9183x over previous
#include <cuda_runtime.h>
#include <math_constants.h>

#define H_IMG 256
#define W_IMG 256
#define A_ANG 64
#define DC_DET 1024
#define NSAMP 512
#define NPAD 2048
#define FEAT 32
#define NPIX (H_IMG * W_IMG)

// ---------------- scratch (device globals: allocation-free) ----------------
// Only referenced from DEVICE code (host-side use of a __device__ symbol gives
// the host shadow address — round-1 bug).
__device__ float g_sino[A_ANG * DC_DET];
__device__ float g_h[NPAD];
__device__ float g_filt[A_ANG * DC_DET];
__device__ float g_xinput[NPIX];
__device__ float g_feat1[FEAT * NPIX];
__device__ float g_xforward[FEAT * NPIX];
__device__ float g_hs[FEAT * NPIX];
__device__ float g_t1[FEAT * NPIX];
__device__ float g_t2[FEAT * NPIX];

// ---------------- f32x2 packed-FMA helpers (Blackwell) ----------------
typedef unsigned long long u64t;
__device__ __forceinline__ u64t pk2(float x) {
    u64t r;
    asm("mov.b64 %0, {%1, %1};" : "=l"(r) : "f"(x));
    return r;
}
__device__ __forceinline__ void fma2(u64t& d, u64t a, u64t b) {
    asm("fma.rn.f32x2 %0, %1, %2, %0;" : "+l"(d) : "l"(a), "l"(b));
}
__device__ __forceinline__ void unpk2(float& lo, float& hi, u64t v) {
    asm("mov.b64 {%0, %1}, %2;" : "=f"(lo), "=f"(hi) : "l"(v));
}

// ---------------- fan-beam forward projection (4 threads / ray) -------------
__device__ __forceinline__ float img_tap(const float* __restrict__ img, int xi, int yi) {
    if ((unsigned)xi < (unsigned)W_IMG && (unsigned)yi < (unsigned)H_IMG)
        return __ldg(&img[yi * W_IMG + xi]);
    return 0.0f;
}

__global__ void k_fanfwd(const float* __restrict__ img, const float* __restrict__ theta) {
    int gid = blockIdx.x * blockDim.x + threadIdx.x;
    int ray = gid >> 2;
    int sub = gid & 3;
    int a = ray >> 10;
    int dc = ray & 1023;
    float th = theta[a];
    float c = cosf(th), s = sinf(th);
    float srcx = 500.0f * c, srcy = 500.0f * s;
    float u = ((float)dc - 511.5f) * 2.0f;
    float dx = -1000.0f * c - u * s;
    float dy = -1000.0f * s + u * c;
    float L = sqrtf(dx * dx + dy * dy);

    // clip t in (0,1) against the padded image box (taps nonzero only there)
    const float lo = -128.51f, hi = 128.51f;
    float tlo = 0.0f, thi = 1.0f;
    {
        if (fabsf(dx) > 1e-9f) {
            float ta = (lo - srcx) / dx, tb = (hi - srcx) / dx;
            tlo = fmaxf(tlo, fminf(ta, tb));
            thi = fminf(thi, fmaxf(ta, tb));
        } else if (srcx < lo || srcx > hi) { thi = -1.0f; }
        if (fabsf(dy) > 1e-9f) {
            float ta = (lo - srcy) / dy, tb = (hi - srcy) / dy;
            tlo = fmaxf(tlo, fminf(ta, tb));
            thi = fminf(thi, fmaxf(ta, tb));
        } else if (srcy < lo || srcy > hi) { thi = -1.0f; }
    }
    float acc = 0.0f;
    if (thi > tlo) {
        int kmin = (int)ceilf(tlo * (float)NSAMP - 0.5f) - 1;
        int kmax = (int)floorf(thi * (float)NSAMP - 0.5f) + 1;
        kmin = max(kmin, 0);
        kmax = min(kmax, NSAMP - 1);
        for (int k = kmin + sub; k <= kmax; k += 4) {
            float t = ((float)k + 0.5f) * (1.0f / (float)NSAMP);
            float px = fmaf(t, dx, srcx);
            float py = fmaf(t, dy, srcy);
            float cx = px + 127.5f, cy = py + 127.5f;
            float x0 = floorf(cx), y0 = floorf(cy);
            float fx = cx - x0, fy = cy - y0;
            int xi = (int)x0, yi = (int)y0;
            float v00 = img_tap(img, xi, yi);
            float v01 = img_tap(img, xi + 1, yi);
            float v10 = img_tap(img, xi, yi + 1);
            float v11 = img_tap(img, xi + 1, yi + 1);
            float vx0 = fmaf(fx, v01 - v00, v00);
            float vx1 = fmaf(fx, v11 - v10, v10);
            acc += fmaf(fy, vx1 - vx0, vx0);
        }
    }
    acc += __shfl_xor_sync(0xFFFFFFFFu, acc, 1);
    acc += __shfl_xor_sync(0xFFFFFFFFu, acc, 2);
    if (sub == 0) g_sino[ray] = acc * (L * (1.0f / (float)NSAMP));
}

// ---------------- Ram-Lak impulse response ----------------
// h[j] = (1/2048) * [ (1/512) * sum_{k=1}^{1023} k*cos(pi*k*j/1024) + (-1)^j ]
__global__ void k_ramp() {
    int j = blockIdx.x;
    double part = 0.0;
    for (int k = 1 + threadIdx.x; k < 1024; k += 128) {
        int p = (k * j) & 2047;
        int r = (p > 1024) ? (2048 - p) : p;
        float sg = 1.0f;
        if (r > 512) { r = 1024 - r; sg = -1.0f; }
        float cv = sg * cosf((float)r * (float)(CUDART_PI / 1024.0));
        part += (double)((float)k * cv);
    }
    __shared__ double red[128];
    red[threadIdx.x] = part;
    __syncthreads();
    for (int s2 = 64; s2 > 0; s2 >>= 1) {
        if (threadIdx.x < s2) red[threadIdx.x] += red[threadIdx.x + s2];
        __syncthreads();
    }
    if (threadIdx.x == 0) {
        double v = red[0] * (1.0 / 512.0) + ((j & 1) ? -1.0 : 1.0);
        g_h[j] = (float)(v * (1.0 / 2048.0));
    }
}

// ---------------- ramp filtering (circular conv with zero-pad) - sinogram ----
__global__ void k_filter(const float* __restrict__ obs) {
    __shared__ float xs[DC_DET];
    __shared__ float hs[NPAD];
    int a = blockIdx.x >> 2;
    int seg = blockIdx.x & 3;
    for (int i = threadIdx.x; i < DC_DET; i += 256) xs[i] = g_sino[a * DC_DET + i];
    for (int i = threadIdx.x; i < NPAD; i += 256) hs[i] = g_h[i];
    __syncthreads();
    int n = seg * 256 + threadIdx.x;
    float acc = 0.0f;
#pragma unroll 8
    for (int m = 0; m < DC_DET; ++m)
        acc = fmaf(xs[m], hs[(n - m) & (NPAD - 1)], acc);
    g_filt[a * DC_DET + n] = acc - obs[a * DC_DET + n];
}

// ---------------- backprojection + x_input (2 threads / pixel) --------------
__global__ void k_backproj(const float* __restrict__ theta, const float* __restrict__ x_in,
                           const float* __restrict__ lam_p) {
    __shared__ float cs[A_ANG], ss[A_ANG];
    int tid = threadIdx.x;
    if (tid < A_ANG) {
        float th = theta[tid];
        cs[tid] = cosf(th);
        ss[tid] = sinf(th);
    }
    __syncthreads();
    int pix = blockIdx.x * 128 + (tid >> 1);
    int half = tid & 1;
    int py = pix >> 8, px = pix & 255;
    float gx = (float)px - 127.5f;
    float gy = (float)py - 127.5f;
    float acc = 0.0f;
    int a0 = half * 32;
#pragma unroll 8
    for (int j = 0; j < 32; ++j) {
        int a = a0 + j;
        float c = cs[a], s = ss[a];
        float xr = gx * c + gy * s;
        float yr = -gx * s + gy * c;
        float invd = __fdividef(1.0f, 500.0f - xr);
        float uu = yr * 1000.0f * invd;
        float wgt = 250000.0f * invd * invd;
        float iu = uu * 0.5f + 511.5f;
        float i0f = floorf(iu);
        float fr = iu - i0f;
        int i0 = (int)i0f;
        const float* row = g_filt + a * DC_DET;
        float v0 = ((unsigned)i0 < (unsigned)DC_DET) ? __ldg(&row[i0]) : 0.0f;
        float v1 = ((unsigned)(i0 + 1) < (unsigned)DC_DET) ? __ldg(&row[i0 + 1]) : 0.0f;
        acc = fmaf(wgt, fmaf(fr, v1 - v0, v0), acc);
    }
    acc += __shfl_xor_sync(0xFFFFFFFFu, acc, 1);
    if (half == 0) {
        float lam = __ldg(lam_p);
        g_xinput[pix] = x_in[pix] - lam * acc * (float)(CUDART_PI / 64.0);
    }
}

// ---------------- conv 1->32 (3x3, SAME) + relu : g_xinput -> g_feat1 --------
__global__ void k_conv1f(const float* __restrict__ w) {
    __shared__ float ws[9][32];
    int tid = threadIdx.x;
    for (int i = tid; i < 288; i += 256) {
        int k = i >> 5, oc = i & 31;
        ws[k][oc] = w[oc * 9 + k];
    }
    __syncthreads();
    int pix = blockIdx.x * 256 + tid;
    int py = pix >> 8, px = pix & 255;
    float pv[9];
#pragma unroll
    for (int dy = 0; dy < 3; ++dy)
#pragma unroll
        for (int dxk = 0; dxk < 3; ++dxk) {
            int yy = py - 1 + dy, xx = px - 1 + dxk;
            pv[dy * 3 + dxk] = ((unsigned)yy < (unsigned)H_IMG && (unsigned)xx < (unsigned)W_IMG)
                                   ? __ldg(&g_xinput[yy * W_IMG + xx]) : 0.0f;
        }
    float acc[32];
#pragma unroll
    for (int o = 0; o < 32; ++o) acc[o] = 0.0f;
#pragma unroll
    for (int k = 0; k < 9; ++k) {
#pragma unroll
        for (int o4 = 0; o4 < 8; ++o4) {
            float4 wv = *(const float4*)&ws[k][o4 * 4];
            acc[o4 * 4 + 0] = fmaf(pv[k], wv.x, acc[o4 * 4 + 0]);
            acc[o4 * 4 + 1] = fmaf(pv[k], wv.y, acc[o4 * 4 + 1]);
            acc[o4 * 4 + 2] = fmaf(pv[k], wv.z, acc[o4 * 4 + 2]);
            acc[o4 * 4 + 3] = fmaf(pv[k], wv.w, acc[o4 * 4 + 3]);
        }
    }
#pragma unroll
    for (int o = 0; o < 32; ++o)
        g_feat1[o * NPIX + pix] = fmaxf(acc[o], 0.0f);
}

// ---------------- conv 32->32 (3x3, SAME), f32x2-packed over oc pairs -------
// VARIANT 0: g_feat1    -> g_xforward (plain) + g_hs (soft-threshold)
// VARIANT 1: g_hs       -> g_t1 (relu)
// VARIANT 2: g_xforward -> g_t2 (relu)
template <int VARIANT>
__global__ void __launch_bounds__(128) k_conv32(const float* __restrict__ w,
                                                const float* __restrict__ thr_p) {
    const float* __restrict__ in =
        (VARIANT == 0) ? g_feat1 : ((VARIANT == 1) ? g_hs : g_xforward);
    float* __restrict__ out =
        (VARIANT == 0) ? g_xforward : ((VARIANT == 1) ? g_t1 : g_t2);

    __shared__ __align__(16) float ws[32][9][32];  // [ic][tap][oc]
    __shared__ float ins[8][18][18];               // 8-ic chunk of 16x16 tile + halo
    int tid = threadIdx.x;
    for (int i = tid; i < 32 * 9 * 32; i += 128) {
        int oc = i / 288;
        int r = i - oc * 288;
        int ic = r / 9;
        int k = r - ic * 9;
        ws[ic][k][oc] = w[i];
    }
    int bx = blockIdx.x & 15, by = blockIdx.x >> 4;
    int tx0 = bx * 16, ty0 = by * 16;
    int lx = tid & 15, ly = tid >> 4;  // ly in [0,8): rows ly and ly+8

    u64t acc0[16], acc1[16];  // (oc even, oc odd) packed pairs for 2 pixels
#pragma unroll
    for (int o = 0; o < 16; ++o) { acc0[o] = 0ull; acc1[o] = 0ull; }

    for (int cc = 0; cc < 4; ++cc) {
        __syncthreads();
        for (int i = tid; i < 8 * 18 * 18; i += 128) {
            int icc = i / 324;
            int rr = (i - icc * 324) / 18;
            int c2 = i - icc * 324 - rr * 18;
            int gy = ty0 - 1 + rr, gx2 = tx0 - 1 + c2;
            float v = 0.0f;
            if ((unsigned)gy < (unsigned)H_IMG && (unsigned)gx2 < (unsigned)W_IMG)
                v = in[(cc * 8 + icc) * NPIX + gy * W_IMG + gx2];
            ins[icc][rr][c2] = v;
        }
        __syncthreads();
#pragma unroll
        for (int icc = 0; icc < 8; ++icc) {
            int ic = cc * 8 + icc;
#pragma unroll
            for (int k = 0; k < 9; ++k) {
                int dy = k / 3, dxk = k - dy * 3;
                u64t p0 = pk2(ins[icc][ly + dy][lx + dxk]);
                u64t p1 = pk2(ins[icc][ly + 8 + dy][lx + dxk]);
#pragma unroll
                for (int o4 = 0; o4 < 8; ++o4) {
                    ulonglong2 wq = *(const ulonglong2*)&ws[ic][k][o4 * 4];
                    fma2(acc0[o4 * 2 + 0], p0, wq.x);
                    fma2(acc0[o4 * 2 + 1], p0, wq.y);
                    fma2(acc1[o4 * 2 + 0], p1, wq.x);
                    fma2(acc1[o4 * 2 + 1], p1, wq.y);
                }
            }
        }
    }
    int x = tx0 + lx;
    int yA = ty0 + ly, yB = yA + 8;
    float thr = (VARIANT == 0) ? __ldg(thr_p) : 0.0f;
#pragma unroll
    for (int j = 0; j < 16; ++j) {
        float v0a, v0b, v1a, v1b;
        unpk2(v0a, v0b, acc0[j]);
        unpk2(v1a, v1b, acc1[j]);
        int oA = 2 * j, oB = 2 * j + 1;
        if (VARIANT != 0) {
            v0a = fmaxf(v0a, 0.0f); v0b = fmaxf(v0b, 0.0f);
            v1a = fmaxf(v1a, 0.0f); v1b = fmaxf(v1b, 0.0f);
        }
        out[oA * NPIX + yA * W_IMG + x] = v0a;
        out[oB * NPIX + yA * W_IMG + x] = v0b;
        out[oA * NPIX + yB * W_IMG + x] = v1a;
        out[oB * NPIX + yB * W_IMG + x] = v1b;
        if (VARIANT == 0) {
            float m0a = fmaxf(fabsf(v0a) - thr, 0.0f);
            float m0b = fmaxf(fabsf(v0b) - thr, 0.0f);
            float m1a = fmaxf(fabsf(v1a) - thr, 0.0f);
            float m1b = fmaxf(fabsf(v1b) - thr, 0.0f);
            g_hs[oA * NPIX + yA * W_IMG + x] = (v0a > 0.0f) ? m0a : ((v0a < 0.0f) ? -m0a : 0.0f);
            g_hs[oB * NPIX + yA * W_IMG + x] = (v0b > 0.0f) ? m0b : ((v0b < 0.0f) ? -m0b : 0.0f);
            g_hs[oA * NPIX + yB * W_IMG + x] = (v1a > 0.0f) ? m1a : ((v1a < 0.0f) ? -m1a : 0.0f);
            g_hs[oB * NPIX + yB * W_IMG + x] = (v1b > 0.0f) ? m1b : ((v1b < 0.0f) ? -m1b : 0.0f);
        }
    }
}

// ---------------- conv 32->1 (3x3, SAME), optional subtract (symloss) --------
// SUB 0: in = g_t1, out = x_pred      SUB 1: in = g_t2, out = x_est - x_input
template <int SUB>
__global__ void k_conv32to1(const float* __restrict__ w, float* __restrict__ out) {
    const float* __restrict__ in = SUB ? g_t2 : g_t1;
    __shared__ float ws[288];
    __shared__ float ins[8][18][18];
    int tid = threadIdx.x;  // 256 threads, 16x16 tile
    for (int i = tid; i < 288; i += 256) ws[i] = w[i];  // (1,32,3,3): w[ic*9+k]
    int bx = blockIdx.x & 15, by = blockIdx.x >> 4;
    int tx0 = bx * 16, ty0 = by * 16;
    int lx = tid & 15, ly = tid >> 4;  // ly in [0,16)
    float acc = 0.0f;
    for (int cc = 0; cc < 4; ++cc) {
        __syncthreads();
        for (int i = tid; i < 8 * 18 * 18; i += 256) {
            int icc = i / 324;
            int rr = (i - icc * 324) / 18;
            int c2 = i - icc * 324 - rr * 18;
            int gy = ty0 - 1 + rr, gx2 = tx0 - 1 + c2;
            float v = 0.0f;
            if ((unsigned)gy < (unsigned)H_IMG && (unsigned)gx2 < (unsigned)W_IMG)
                v = in[(cc * 8 + icc) * NPIX + gy * W_IMG + gx2];
            ins[icc][rr][c2] = v;
        }
        __syncthreads();
#pragma unroll
        for (int icc = 0; icc < 8; ++icc) {
            int ic = cc * 8 + icc;
#pragma unroll
            for (int dy = 0; dy < 3; ++dy)
#pragma unroll
                for (int dxk = 0; dxk < 3; ++dxk)
                    acc = fmaf(ins[icc][ly + dy][lx + dxk], ws[ic * 9 + dy * 3 + dxk], acc);
        }
    }
    int pix = (ty0 + ly) * W_IMG + tx0 + lx;
    out[pix] = SUB ? (acc - g_xinput[pix]) : acc;
}

// ---------------- launch ----------------
extern "C" void kernel_launch(void* const* d_in, const int* in_sizes, int n_in,
                              void* d_out, int out_size) {
    const float* x        = (const float*)d_in[0];
    const float* theta    = (const float*)d_in[1];
    const float* sinogram = (const float*)d_in[2];
    const float* lam      = (const float*)d_in[3];
    const float* thr      = (const float*)d_in[4];
    const float* w1f      = (const float*)d_in[5];
    const float* w2f      = (const float*)d_in[6];
    const float* w1b      = (const float*)d_in[7];
    const float* w2b      = (const float*)d_in[8];
    float* out = (float*)d_out;  // [0:65536) x_pred, [65536:131072) symloss

    k_fanfwd<<<1024, 256>>>(x, theta);          // 4 threads / ray
    k_ramp<<<NPAD, 128>>>();
    k_filter<<<A_ANG * 4, 256>>>(sinogram);
    k_backproj<<<512, 256>>>(theta, x, lam);    // 2 threads / pixel
    k_conv1f<<<256, 256>>>(w1f);
    k_conv32<0><<<256, 128>>>(w2f, thr);
    k_conv32<1><<<256, 128>>>(w1b, nullptr);
    k_conv32<2><<<256, 128>>>(w1b, nullptr);
    k_conv32to1<0><<<256, 256>>>(w2b, out);
    k_conv32to1<1><<<256, 256>>>(w2b, out + NPIX);
}

// round 4
// speedup vs baseline: 2.1865x; 1.1398x over previous
#include <cuda_runtime.h>
#include <math_constants.h>

#define H_IMG 256
#define W_IMG 256
#define A_ANG 64
#define DC_DET 1024
#define NSAMP 512
#define NPAD 2048
#define FEAT 32
#define NPIX (H_IMG * W_IMG)

// ---------------- scratch (device globals: allocation-free) ----------------
__device__ float g_sino[A_ANG * DC_DET];
__device__ float g_h[NPAD];
__device__ float g_filt[A_ANG * DC_DET];
__device__ float g_xinput[NPIX];
__device__ float g_feat1[FEAT * NPIX];
__device__ float g_xforward[FEAT * NPIX];
__device__ float g_hs[FEAT * NPIX];
__device__ float g_t1[FEAT * NPIX];
__device__ float g_t2[FEAT * NPIX];

// ---------------- f32x2 packed-FMA helpers (Blackwell) ----------------
typedef unsigned long long u64t;
__device__ __forceinline__ u64t pk2(float x) {
    u64t r;
    asm("mov.b64 %0, {%1, %1};" : "=l"(r) : "f"(x));
    return r;
}
__device__ __forceinline__ void fma2(u64t& d, u64t a, u64t b) {
    asm("fma.rn.f32x2 %0, %1, %2, %0;" : "+l"(d) : "l"(a), "l"(b));
}
__device__ __forceinline__ void unpk2(float& lo, float& hi, u64t v) {
    asm("mov.b64 {%0, %1}, %2;" : "=f"(lo), "=f"(hi) : "l"(v));
}

// ---------------- fan-beam forward projection (8 threads / ray) -------------
__device__ __forceinline__ float img_tap(const float* __restrict__ img, int xi, int yi) {
    if ((unsigned)xi < (unsigned)W_IMG && (unsigned)yi < (unsigned)H_IMG)
        return __ldg(&img[yi * W_IMG + xi]);
    return 0.0f;
}

__global__ void k_fanfwd(const float* __restrict__ img, const float* __restrict__ theta) {
    int gid = blockIdx.x * blockDim.x + threadIdx.x;
    int ray = gid >> 3;
    int sub = gid & 7;
    int a = ray >> 10;
    int dc = ray & 1023;
    float th = theta[a];
    float c = cosf(th), s = sinf(th);
    float srcx = 500.0f * c, srcy = 500.0f * s;
    float u = ((float)dc - 511.5f) * 2.0f;
    float dx = -1000.0f * c - u * s;
    float dy = -1000.0f * s + u * c;
    float L = sqrtf(dx * dx + dy * dy);

    // clip t in (0,1) against the padded image box (taps nonzero only there)
    const float lo = -128.51f, hi = 128.51f;
    float tlo = 0.0f, thi = 1.0f;
    {
        if (fabsf(dx) > 1e-9f) {
            float ta = (lo - srcx) / dx, tb = (hi - srcx) / dx;
            tlo = fmaxf(tlo, fminf(ta, tb));
            thi = fminf(thi, fmaxf(ta, tb));
        } else if (srcx < lo || srcx > hi) { thi = -1.0f; }
        if (fabsf(dy) > 1e-9f) {
            float ta = (lo - srcy) / dy, tb = (hi - srcy) / dy;
            tlo = fmaxf(tlo, fminf(ta, tb));
            thi = fminf(thi, fmaxf(ta, tb));
        } else if (srcy < lo || srcy > hi) { thi = -1.0f; }
    }
    float acc = 0.0f;
    if (thi > tlo) {
        int kmin = (int)ceilf(tlo * (float)NSAMP - 0.5f) - 1;
        int kmax = (int)floorf(thi * (float)NSAMP - 0.5f) + 1;
        kmin = max(kmin, 0);
        kmax = min(kmax, NSAMP - 1);
        for (int k = kmin + sub; k <= kmax; k += 8) {
            float t = ((float)k + 0.5f) * (1.0f / (float)NSAMP);
            float px = fmaf(t, dx, srcx);
            float py = fmaf(t, dy, srcy);
            float cx = px + 127.5f, cy = py + 127.5f;
            float x0 = floorf(cx), y0 = floorf(cy);
            float fx = cx - x0, fy = cy - y0;
            int xi = (int)x0, yi = (int)y0;
            float v00 = img_tap(img, xi, yi);
            float v01 = img_tap(img, xi + 1, yi);
            float v10 = img_tap(img, xi, yi + 1);
            float v11 = img_tap(img, xi + 1, yi + 1);
            float vx0 = fmaf(fx, v01 - v00, v00);
            float vx1 = fmaf(fx, v11 - v10, v10);
            acc += fmaf(fy, vx1 - vx0, vx0);
        }
    }
    acc += __shfl_xor_sync(0xFFFFFFFFu, acc, 1);
    acc += __shfl_xor_sync(0xFFFFFFFFu, acc, 2);
    acc += __shfl_xor_sync(0xFFFFFFFFu, acc, 4);
    if (sub == 0) g_sino[ray] = acc * (L * (1.0f / (float)NSAMP));
}

// ---------------- Ram-Lak impulse response (closed form, exact) -------------
// h[j] = (1/2048) [ S_j/512 + (-1)^j ], S_j = sum_{k=1}^{1023} k cos(pi k j/1024)
//      S_j = [ -(1+1023 p) + 1024 p cos(th) ] / (4 sin^2(th/2)),  p=(-1)^j
__global__ void k_ramp() {
    int j = blockIdx.x * blockDim.x + threadIdx.x;
    double hj;
    if (j == 0) {
        hj = 0.5;  // S_0/512 = 1023, (1023+1)/2048
    } else {
        double th = (double)j * (CUDART_PI / 1024.0);
        double p = (j & 1) ? -1.0 : 1.0;
        double sh = sin(0.5 * th);
        double S = (-(1.0 + 1023.0 * p) + 1024.0 * p * cos(th)) / (4.0 * sh * sh);
        hj = (S * (1.0 / 512.0) + p) * (1.0 / 2048.0);
    }
    g_h[j] = (float)hj;
}

// ---------------- ramp filtering (circular conv with zero-pad) - sinogram ----
__global__ void k_filter(const float* __restrict__ obs) {
    __shared__ float xs[DC_DET];
    __shared__ float hs[NPAD];
    int a = blockIdx.x >> 2;
    int seg = blockIdx.x & 3;
    for (int i = threadIdx.x; i < DC_DET; i += 256) xs[i] = g_sino[a * DC_DET + i];
    for (int i = threadIdx.x; i < NPAD; i += 256) hs[i] = g_h[i];
    __syncthreads();
    int n = seg * 256 + threadIdx.x;
    float acc = 0.0f;
#pragma unroll 8
    for (int m = 0; m < DC_DET; ++m)
        acc = fmaf(xs[m], hs[(n - m) & (NPAD - 1)], acc);
    g_filt[a * DC_DET + n] = acc - obs[a * DC_DET + n];
}

// ---------------- backprojection + x_input (4 threads / pixel) --------------
__global__ void k_backproj(const float* __restrict__ theta, const float* __restrict__ x_in,
                           const float* __restrict__ lam_p) {
    __shared__ float cs[A_ANG], ss[A_ANG];
    int tid = threadIdx.x;
    if (tid < A_ANG) {
        float th = theta[tid];
        cs[tid] = cosf(th);
        ss[tid] = sinf(th);
    }
    __syncthreads();
    int pix = blockIdx.x * 64 + (tid >> 2);
    int quad = tid & 3;
    int py = pix >> 8, px = pix & 255;
    float gx = (float)px - 127.5f;
    float gy = (float)py - 127.5f;
    float accA = 0.0f, accB = 0.0f;
    int a0 = quad * 16;
#pragma unroll
    for (int j = 0; j < 16; j += 2) {
#pragma unroll
        for (int half = 0; half < 2; ++half) {
            int a = a0 + j + half;
            float c = cs[a], s = ss[a];
            float xr = gx * c + gy * s;
            float yr = -gx * s + gy * c;
            float invd = __fdividef(1.0f, 500.0f - xr);
            float uu = yr * 1000.0f * invd;
            float wgt = 250000.0f * invd * invd;
            float iu = uu * 0.5f + 511.5f;
            float i0f = floorf(iu);
            float fr = iu - i0f;
            int i0 = (int)i0f;
            const float* row = g_filt + a * DC_DET;
            float v0 = ((unsigned)i0 < (unsigned)DC_DET) ? __ldg(&row[i0]) : 0.0f;
            float v1 = ((unsigned)(i0 + 1) < (unsigned)DC_DET) ? __ldg(&row[i0 + 1]) : 0.0f;
            float term = wgt * fmaf(fr, v1 - v0, v0);
            if (half == 0) accA += term; else accB += term;
        }
    }
    float acc = accA + accB;
    acc += __shfl_xor_sync(0xFFFFFFFFu, acc, 1);
    acc += __shfl_xor_sync(0xFFFFFFFFu, acc, 2);
    if (quad == 0) {
        float lam = __ldg(lam_p);
        g_xinput[pix] = x_in[pix] - lam * acc * (float)(CUDART_PI / 64.0);
    }
}

// ---------------- conv 1->32 (3x3, SAME) + relu : g_xinput -> g_feat1 --------
__global__ void k_conv1f(const float* __restrict__ w) {
    __shared__ float ws[9][32];
    int tid = threadIdx.x;
    for (int i = tid; i < 288; i += 256) {
        int k = i >> 5, oc = i & 31;
        ws[k][oc] = w[oc * 9 + k];
    }
    __syncthreads();
    int pix = blockIdx.x * 256 + tid;
    int py = pix >> 8, px = pix & 255;
    float pv[9];
#pragma unroll
    for (int dy = 0; dy < 3; ++dy)
#pragma unroll
        for (int dxk = 0; dxk < 3; ++dxk) {
            int yy = py - 1 + dy, xx = px - 1 + dxk;
            pv[dy * 3 + dxk] = ((unsigned)yy < (unsigned)H_IMG && (unsigned)xx < (unsigned)W_IMG)
                                   ? __ldg(&g_xinput[yy * W_IMG + xx]) : 0.0f;
        }
    float acc[32];
#pragma unroll
    for (int o = 0; o < 32; ++o) acc[o] = 0.0f;
#pragma unroll
    for (int k = 0; k < 9; ++k) {
#pragma unroll
        for (int o4 = 0; o4 < 8; ++o4) {
            float4 wv = *(const float4*)&ws[k][o4 * 4];
            acc[o4 * 4 + 0] = fmaf(pv[k], wv.x, acc[o4 * 4 + 0]);
            acc[o4 * 4 + 1] = fmaf(pv[k], wv.y, acc[o4 * 4 + 1]);
            acc[o4 * 4 + 2] = fmaf(pv[k], wv.z, acc[o4 * 4 + 2]);
            acc[o4 * 4 + 3] = fmaf(pv[k], wv.w, acc[o4 * 4 + 3]);
        }
    }
#pragma unroll
    for (int o = 0; o < 32; ++o)
        g_feat1[o * NPIX + pix] = fmaxf(acc[o], 0.0f);
}

// ---------------- conv 32->32 core (f32x2 over oc pairs) --------------------
// Computes one 16x16 tile (2 pixels/thread) of a 32ic->32oc 3x3 SAME conv.
template <bool SOFT>  // SOFT: plain out + soft-threshold out2; else relu out
__device__ __forceinline__ void conv32_tile(const float* __restrict__ in,
                                            float* __restrict__ out,
                                            float* __restrict__ out2,
                                            const float* __restrict__ thr_p,
                                            const float* __restrict__ w,
                                            int tile, int tid) {
    __shared__ __align__(16) float ws[32][9][32];  // [ic][tap][oc]
    __shared__ float ins[8][18][18];
    for (int i = tid; i < 32 * 9 * 32; i += 128) {
        int oc = i / 288;
        int r = i - oc * 288;
        int ic = r / 9;
        int k = r - ic * 9;
        ws[ic][k][oc] = w[i];
    }
    int bx = tile & 15, by = tile >> 4;
    int tx0 = bx * 16, ty0 = by * 16;
    int lx = tid & 15, ly = tid >> 4;  // ly in [0,8)

    u64t acc0[16], acc1[16];
#pragma unroll
    for (int o = 0; o < 16; ++o) { acc0[o] = 0ull; acc1[o] = 0ull; }

    for (int cc = 0; cc < 4; ++cc) {
        __syncthreads();
        for (int i = tid; i < 8 * 18 * 18; i += 128) {
            int icc = i / 324;
            int rr = (i - icc * 324) / 18;
            int c2 = i - icc * 324 - rr * 18;
            int gy = ty0 - 1 + rr, gx2 = tx0 - 1 + c2;
            float v = 0.0f;
            if ((unsigned)gy < (unsigned)H_IMG && (unsigned)gx2 < (unsigned)W_IMG)
                v = in[(cc * 8 + icc) * NPIX + gy * W_IMG + gx2];
            ins[icc][rr][c2] = v;
        }
        __syncthreads();
#pragma unroll
        for (int icc = 0; icc < 8; ++icc) {
            int ic = cc * 8 + icc;
#pragma unroll
            for (int k = 0; k < 9; ++k) {
                int dy = k / 3, dxk = k - dy * 3;
                u64t p0 = pk2(ins[icc][ly + dy][lx + dxk]);
                u64t p1 = pk2(ins[icc][ly + 8 + dy][lx + dxk]);
#pragma unroll
                for (int o4 = 0; o4 < 8; ++o4) {
                    ulonglong2 wq = *(const ulonglong2*)&ws[ic][k][o4 * 4];
                    fma2(acc0[o4 * 2 + 0], p0, wq.x);
                    fma2(acc0[o4 * 2 + 1], p0, wq.y);
                    fma2(acc1[o4 * 2 + 0], p1, wq.x);
                    fma2(acc1[o4 * 2 + 1], p1, wq.y);
                }
            }
        }
    }
    int x = tx0 + lx;
    int yA = ty0 + ly, yB = yA + 8;
    float thr = SOFT ? __ldg(thr_p) : 0.0f;
#pragma unroll
    for (int j = 0; j < 16; ++j) {
        float v0a, v0b, v1a, v1b;
        unpk2(v0a, v0b, acc0[j]);
        unpk2(v1a, v1b, acc1[j]);
        int oA = 2 * j, oB = 2 * j + 1;
        if (!SOFT) {
            v0a = fmaxf(v0a, 0.0f); v0b = fmaxf(v0b, 0.0f);
            v1a = fmaxf(v1a, 0.0f); v1b = fmaxf(v1b, 0.0f);
        }
        out[oA * NPIX + yA * W_IMG + x] = v0a;
        out[oB * NPIX + yA * W_IMG + x] = v0b;
        out[oA * NPIX + yB * W_IMG + x] = v1a;
        out[oB * NPIX + yB * W_IMG + x] = v1b;
        if (SOFT) {
            float m0a = fmaxf(fabsf(v0a) - thr, 0.0f);
            float m0b = fmaxf(fabsf(v0b) - thr, 0.0f);
            float m1a = fmaxf(fabsf(v1a) - thr, 0.0f);
            float m1b = fmaxf(fabsf(v1b) - thr, 0.0f);
            out2[oA * NPIX + yA * W_IMG + x] = (v0a > 0.0f) ? m0a : ((v0a < 0.0f) ? -m0a : 0.0f);
            out2[oB * NPIX + yA * W_IMG + x] = (v0b > 0.0f) ? m0b : ((v0b < 0.0f) ? -m0b : 0.0f);
            out2[oA * NPIX + yB * W_IMG + x] = (v1a > 0.0f) ? m1a : ((v1a < 0.0f) ? -m1a : 0.0f);
            out2[oB * NPIX + yB * W_IMG + x] = (v1b > 0.0f) ? m1b : ((v1b < 0.0f) ? -m1b : 0.0f);
        }
    }
}

// stage A: g_feat1 -> g_xforward (plain) + g_hs (soft-threshold)
__global__ void __launch_bounds__(128) k_conv32a(const float* __restrict__ w,
                                                 const float* __restrict__ thr_p) {
    conv32_tile<true>(g_feat1, g_xforward, g_hs, thr_p, w, blockIdx.x, threadIdx.x);
}

// stage B (merged): blocks [0,256): g_hs -> g_t1 (relu); [256,512): g_xforward -> g_t2 (relu)
__global__ void __launch_bounds__(128) k_conv32b(const float* __restrict__ w) {
    int which = blockIdx.x >> 8;
    const float* in = which ? g_xforward : g_hs;
    float* out = which ? g_t2 : g_t1;
    conv32_tile<false>(in, out, nullptr, nullptr, w, blockIdx.x & 255, threadIdx.x);
}

// ---------------- conv 32->1 (3x3, SAME), merged pair ------------------------
// blocks [0,256): g_t1 -> out (x_pred); [256,512): g_t2 -> out+NPIX (- x_input)
__global__ void k_conv32to1(const float* __restrict__ w, float* __restrict__ outbase) {
    int sub = blockIdx.x >> 8;
    int tile = blockIdx.x & 255;
    const float* __restrict__ in = sub ? g_t2 : g_t1;
    float* __restrict__ out = outbase + sub * NPIX;
    __shared__ float ws[288];
    __shared__ float ins[8][18][18];
    int tid = threadIdx.x;  // 256 threads, 16x16 tile
    for (int i = tid; i < 288; i += 256) ws[i] = w[i];
    int bx = tile & 15, by = tile >> 4;
    int tx0 = bx * 16, ty0 = by * 16;
    int lx = tid & 15, ly = tid >> 4;
    float acc = 0.0f;
    for (int cc = 0; cc < 4; ++cc) {
        __syncthreads();
        for (int i = tid; i < 8 * 18 * 18; i += 256) {
            int icc = i / 324;
            int rr = (i - icc * 324) / 18;
            int c2 = i - icc * 324 - rr * 18;
            int gy = ty0 - 1 + rr, gx2 = tx0 - 1 + c2;
            float v = 0.0f;
            if ((unsigned)gy < (unsigned)H_IMG && (unsigned)gx2 < (unsigned)W_IMG)
                v = in[(cc * 8 + icc) * NPIX + gy * W_IMG + gx2];
            ins[icc][rr][c2] = v;
        }
        __syncthreads();
#pragma unroll
        for (int icc = 0; icc < 8; ++icc) {
            int ic = cc * 8 + icc;
#pragma unroll
            for (int dy = 0; dy < 3; ++dy)
#pragma unroll
                for (int dxk = 0; dxk < 3; ++dxk)
                    acc = fmaf(ins[icc][ly + dy][lx + dxk], ws[ic * 9 + dy * 3 + dxk], acc);
        }
    }
    int pix = (ty0 + ly) * W_IMG + tx0 + lx;
    out[pix] = sub ? (acc - g_xinput[pix]) : acc;
}

// ---------------- launch ----------------
extern "C" void kernel_launch(void* const* d_in, const int* in_sizes, int n_in,
                              void* d_out, int out_size) {
    const float* x        = (const float*)d_in[0];
    const float* theta    = (const float*)d_in[1];
    const float* sinogram = (const float*)d_in[2];
    const float* lam      = (const float*)d_in[3];
    const float* thr      = (const float*)d_in[4];
    const float* w1f      = (const float*)d_in[5];
    const float* w2f      = (const float*)d_in[6];
    const float* w1b      = (const float*)d_in[7];
    const float* w2b      = (const float*)d_in[8];
    float* out = (float*)d_out;  // [0:65536) x_pred, [65536:131072) symloss

    k_fanfwd<<<2048, 256>>>(x, theta);          // 8 threads / ray
    k_ramp<<<8, 256>>>();                       // closed form
    k_filter<<<A_ANG * 4, 256>>>(sinogram);
    k_backproj<<<1024, 256>>>(theta, x, lam);   // 4 threads / pixel
    k_conv1f<<<256, 256>>>(w1f);
    k_conv32a<<<256, 128>>>(w2f, thr);
    k_conv32b<<<512, 128>>>(w1b);               // both branches, one launch
    k_conv32to1<<<512, 256>>>(w2b, out);        // both outputs, one launch
}

// round 5
// speedup vs baseline: 2.3104x; 1.0567x over previous
#include <cuda_runtime.h>
#include <math_constants.h>

#define H_IMG 256
#define W_IMG 256
#define A_ANG 64
#define DC_DET 1024
#define NSAMP 512
#define NPAD 2048
#define FEAT 32
#define NPIX (H_IMG * W_IMG)

// ---------------- scratch (device globals: allocation-free) ----------------
__device__ float g_sino[A_ANG * DC_DET];
__device__ float g_filt[A_ANG * DC_DET];
__device__ float g_xinput[NPIX];
__device__ float g_feat1[FEAT * NPIX];
__device__ float g_xforward[FEAT * NPIX];
__device__ float g_hs[FEAT * NPIX];
__device__ float g_t1[FEAT * NPIX];
__device__ float g_t2[FEAT * NPIX];

// ---------------- f32x2 packed-FMA helpers (Blackwell) ----------------
typedef unsigned long long u64t;
__device__ __forceinline__ u64t pk2(float x) {
    u64t r;
    asm("mov.b64 %0, {%1, %1};" : "=l"(r) : "f"(x));
    return r;
}
__device__ __forceinline__ void fma2(u64t& d, u64t a, u64t b) {
    asm("fma.rn.f32x2 %0, %1, %2, %0;" : "+l"(d) : "l"(a), "l"(b));
}
__device__ __forceinline__ void unpk2(float& lo, float& hi, u64t v) {
    asm("mov.b64 {%0, %1}, %2;" : "=f"(lo), "=f"(hi) : "l"(v));
}

// ---------------- fan-beam forward projection (8 threads / ray) -------------
__device__ __forceinline__ float img_tap(const float* __restrict__ img, int xi, int yi) {
    if ((unsigned)xi < (unsigned)W_IMG && (unsigned)yi < (unsigned)H_IMG)
        return __ldg(&img[yi * W_IMG + xi]);
    return 0.0f;
}

__global__ void k_fanfwd(const float* __restrict__ img, const float* __restrict__ theta) {
    int gid = blockIdx.x * blockDim.x + threadIdx.x;
    int ray = gid >> 3;
    int sub = gid & 7;
    int a = ray >> 10;
    int dc = ray & 1023;
    float th = theta[a];
    float c = cosf(th), s = sinf(th);
    float srcx = 500.0f * c, srcy = 500.0f * s;
    float u = ((float)dc - 511.5f) * 2.0f;
    float dx = -1000.0f * c - u * s;
    float dy = -1000.0f * s + u * c;
    float L = sqrtf(dx * dx + dy * dy);

    const float lo = -128.51f, hi = 128.51f;
    float tlo = 0.0f, thi = 1.0f;
    {
        if (fabsf(dx) > 1e-9f) {
            float ta = (lo - srcx) / dx, tb = (hi - srcx) / dx;
            tlo = fmaxf(tlo, fminf(ta, tb));
            thi = fminf(thi, fmaxf(ta, tb));
        } else if (srcx < lo || srcx > hi) { thi = -1.0f; }
        if (fabsf(dy) > 1e-9f) {
            float ta = (lo - srcy) / dy, tb = (hi - srcy) / dy;
            tlo = fmaxf(tlo, fminf(ta, tb));
            thi = fminf(thi, fmaxf(ta, tb));
        } else if (srcy < lo || srcy > hi) { thi = -1.0f; }
    }
    float acc = 0.0f;
    if (thi > tlo) {
        int kmin = (int)ceilf(tlo * (float)NSAMP - 0.5f) - 1;
        int kmax = (int)floorf(thi * (float)NSAMP - 0.5f) + 1;
        kmin = max(kmin, 0);
        kmax = min(kmax, NSAMP - 1);
        for (int k = kmin + sub; k <= kmax; k += 8) {
            float t = ((float)k + 0.5f) * (1.0f / (float)NSAMP);
            float px = fmaf(t, dx, srcx);
            float py = fmaf(t, dy, srcy);
            float cx = px + 127.5f, cy = py + 127.5f;
            float x0 = floorf(cx), y0 = floorf(cy);
            float fx = cx - x0, fy = cy - y0;
            int xi = (int)x0, yi = (int)y0;
            float v00 = img_tap(img, xi, yi);
            float v01 = img_tap(img, xi + 1, yi);
            float v10 = img_tap(img, xi, yi + 1);
            float v11 = img_tap(img, xi + 1, yi + 1);
            float vx0 = fmaf(fx, v01 - v00, v00);
            float vx1 = fmaf(fx, v11 - v10, v10);
            acc += fmaf(fy, vx1 - vx0, vx0);
        }
    }
    acc += __shfl_xor_sync(0xFFFFFFFFu, acc, 1);
    acc += __shfl_xor_sync(0xFFFFFFFFu, acc, 2);
    acc += __shfl_xor_sync(0xFFFFFFFFu, acc, 4);
    if (sub == 0) g_sino[ray] = acc * (L * (1.0f / (float)NSAMP));
}

// ---------------- ramp filter, fused closed-form IR ----------------
// h = irfft(2*rfftfreq(2048)):  h[0] = 0.5,  h[even>0] = 0 exactly,
// h[odd j] = -1 / (2^21 * sin^2(j*pi/2048)).
// y[n] = 0.5*x[n] + sum over opposite-parity k<1024 of h[(n-k)&2047]*x[k].
// One block per angle; thread computes 4 consecutive outputs.
__global__ void __launch_bounds__(256) k_filter(const float* __restrict__ obs) {
    __shared__ float xs[DC_DET];
    __shared__ float hodd[1024];  // hodd[i] = h[2i+1]
    int a = blockIdx.x;
    int tid = threadIdx.x;
    for (int i = tid; i < 1024; i += 256) {
        float sh = sinf((float)(2 * i + 1) * 1.5339807878856412e-3f);  // pi/2048
        hodd[i] = -4.76837158203125e-7f / (sh * sh);                   // -1/2^21
    }
    for (int i = tid; i < DC_DET; i += 256) xs[i] = g_sino[a * DC_DET + i];
    __syncthreads();

    int t = tid;            // outputs n = 4t .. 4t+3
    int b2t = 2 * t;
    float a0 = 0.f, a1 = 0.f, a2 = 0.f, a3 = 0.f;
#pragma unroll 4
    for (int kb = 0; kb < 512; kb += 4) {
        float4 X0 = *(float4*)&xs[2 * kb];       // xE0 xO0 xE1 xO1
        float4 X1 = *(float4*)&xs[2 * kb + 4];   // xE2 xO2 xE3 xO3
        int e0 = (b2t - kb - 4) & 1023;          // even
        float2 w01 = *(float2*)&hodd[e0];
        float2 w23 = *(float2*)&hodd[(e0 + 2) & 1023];
        float2 w45 = *(float2*)&hodd[(e0 + 4) & 1023];
        float H0 = w01.x, H1 = w01.y, H2 = w23.x, H3 = w23.y, H4 = w45.x, H5 = w45.y;
        // r=0
        a0 = fmaf(H3, X0.y, a0); a1 = fmaf(H4, X0.x, a1);
        a2 = fmaf(H4, X0.y, a2); a3 = fmaf(H5, X0.x, a3);
        // r=1
        a0 = fmaf(H2, X0.w, a0); a1 = fmaf(H3, X0.z, a1);
        a2 = fmaf(H3, X0.w, a2); a3 = fmaf(H4, X0.z, a3);
        // r=2
        a0 = fmaf(H1, X1.y, a0); a1 = fmaf(H2, X1.x, a1);
        a2 = fmaf(H2, X1.y, a2); a3 = fmaf(H3, X1.x, a3);
        // r=3
        a0 = fmaf(H0, X1.w, a0); a1 = fmaf(H1, X1.z, a1);
        a2 = fmaf(H1, X1.w, a2); a3 = fmaf(H2, X1.z, a3);
    }
    int n = 4 * t;
    float4 xc = *(float4*)&xs[n];
    float4 o4 = *(const float4*)&obs[a * DC_DET + n];
    float4 res;
    res.x = fmaf(0.5f, xc.x, a0) - o4.x;
    res.y = fmaf(0.5f, xc.y, a1) - o4.y;
    res.z = fmaf(0.5f, xc.z, a2) - o4.z;
    res.w = fmaf(0.5f, xc.w, a3) - o4.w;
    *(float4*)&g_filt[a * DC_DET + n] = res;
}

// ---------------- backprojection + x_input (8 threads / pixel) --------------
__global__ void k_backproj(const float* __restrict__ theta, const float* __restrict__ x_in,
                           const float* __restrict__ lam_p) {
    __shared__ float cs[A_ANG], ss[A_ANG];
    int tid = threadIdx.x;
    if (tid < A_ANG) {
        float th = theta[tid];
        cs[tid] = cosf(th);
        ss[tid] = sinf(th);
    }
    __syncthreads();
    int pix = blockIdx.x * 32 + (tid >> 3);
    int oct = tid & 7;
    int py = pix >> 8, px = pix & 255;
    float gx = (float)px - 127.5f;
    float gy = (float)py - 127.5f;
    float accA = 0.0f, accB = 0.0f;
    int a0 = oct * 8;
#pragma unroll
    for (int j = 0; j < 8; j += 2) {
#pragma unroll
        for (int half = 0; half < 2; ++half) {
            int a = a0 + j + half;
            float c = cs[a], s = ss[a];
            float xr = gx * c + gy * s;
            float yr = -gx * s + gy * c;
            float invd = __fdividef(1.0f, 500.0f - xr);
            float uu = yr * 1000.0f * invd;
            float wgt = 250000.0f * invd * invd;
            float iu = uu * 0.5f + 511.5f;
            float i0f = floorf(iu);
            float fr = iu - i0f;
            int i0 = (int)i0f;
            const float* row = g_filt + a * DC_DET;
            float v0 = ((unsigned)i0 < (unsigned)DC_DET) ? __ldg(&row[i0]) : 0.0f;
            float v1 = ((unsigned)(i0 + 1) < (unsigned)DC_DET) ? __ldg(&row[i0 + 1]) : 0.0f;
            float term = wgt * fmaf(fr, v1 - v0, v0);
            if (half == 0) accA += term; else accB += term;
        }
    }
    float acc = accA + accB;
    acc += __shfl_xor_sync(0xFFFFFFFFu, acc, 1);
    acc += __shfl_xor_sync(0xFFFFFFFFu, acc, 2);
    acc += __shfl_xor_sync(0xFFFFFFFFu, acc, 4);
    if (oct == 0) {
        float lam = __ldg(lam_p);
        g_xinput[pix] = x_in[pix] - lam * acc * (float)(CUDART_PI / 64.0);
    }
}

// ---------------- conv 1->32 (3x3, SAME) + relu : g_xinput -> g_feat1 --------
__global__ void k_conv1f(const float* __restrict__ w) {
    __shared__ float ws[9][32];
    int tid = threadIdx.x;
    for (int i = tid; i < 288; i += 256) {
        int k = i >> 5, oc = i & 31;
        ws[k][oc] = w[oc * 9 + k];
    }
    __syncthreads();
    int pix = blockIdx.x * 256 + tid;
    int py = pix >> 8, px = pix & 255;
    float pv[9];
#pragma unroll
    for (int dy = 0; dy < 3; ++dy)
#pragma unroll
        for (int dxk = 0; dxk < 3; ++dxk) {
            int yy = py - 1 + dy, xx = px - 1 + dxk;
            pv[dy * 3 + dxk] = ((unsigned)yy < (unsigned)H_IMG && (unsigned)xx < (unsigned)W_IMG)
                                   ? __ldg(&g_xinput[yy * W_IMG + xx]) : 0.0f;
        }
    float acc[32];
#pragma unroll
    for (int o = 0; o < 32; ++o) acc[o] = 0.0f;
#pragma unroll
    for (int k = 0; k < 9; ++k) {
#pragma unroll
        for (int o4 = 0; o4 < 8; ++o4) {
            float4 wv = *(const float4*)&ws[k][o4 * 4];
            acc[o4 * 4 + 0] = fmaf(pv[k], wv.x, acc[o4 * 4 + 0]);
            acc[o4 * 4 + 1] = fmaf(pv[k], wv.y, acc[o4 * 4 + 1]);
            acc[o4 * 4 + 2] = fmaf(pv[k], wv.z, acc[o4 * 4 + 2]);
            acc[o4 * 4 + 3] = fmaf(pv[k], wv.w, acc[o4 * 4 + 3]);
        }
    }
#pragma unroll
    for (int o = 0; o < 32; ++o)
        g_feat1[o * NPIX + pix] = fmaxf(acc[o], 0.0f);
}

// ---------------- conv 32->32 core (f32x2 over oc pairs) --------------------
template <bool SOFT>
__device__ __forceinline__ void conv32_tile(const float* __restrict__ in,
                                            float* __restrict__ out,
                                            float* __restrict__ out2,
                                            const float* __restrict__ thr_p,
                                            const float* __restrict__ w,
                                            int tile, int tid) {
    __shared__ __align__(16) float ws[32][9][32];  // [ic][tap][oc]
    __shared__ float ins[8][18][18];
    for (int i = tid; i < 32 * 9 * 32; i += 128) {
        int oc = i / 288;
        int r = i - oc * 288;
        int ic = r / 9;
        int k = r - ic * 9;
        ws[ic][k][oc] = w[i];
    }
    int bx = tile & 15, by = tile >> 4;
    int tx0 = bx * 16, ty0 = by * 16;
    int lx = tid & 15, ly = tid >> 4;  // ly in [0,8)

    u64t acc0[16], acc1[16];
#pragma unroll
    for (int o = 0; o < 16; ++o) { acc0[o] = 0ull; acc1[o] = 0ull; }

    for (int cc = 0; cc < 4; ++cc) {
        __syncthreads();
        for (int i = tid; i < 8 * 18 * 18; i += 128) {
            int icc = i / 324;
            int rr = (i - icc * 324) / 18;
            int c2 = i - icc * 324 - rr * 18;
            int gy = ty0 - 1 + rr, gx2 = tx0 - 1 + c2;
            float v = 0.0f;
            if ((unsigned)gy < (unsigned)H_IMG && (unsigned)gx2 < (unsigned)W_IMG)
                v = in[(cc * 8 + icc) * NPIX + gy * W_IMG + gx2];
            ins[icc][rr][c2] = v;
        }
        __syncthreads();
#pragma unroll
        for (int icc = 0; icc < 8; ++icc) {
            int ic = cc * 8 + icc;
#pragma unroll
            for (int k = 0; k < 9; ++k) {
                int dy = k / 3, dxk = k - dy * 3;
                u64t p0 = pk2(ins[icc][ly + dy][lx + dxk]);
                u64t p1 = pk2(ins[icc][ly + 8 + dy][lx + dxk]);
#pragma unroll
                for (int o4 = 0; o4 < 8; ++o4) {
                    ulonglong2 wq = *(const ulonglong2*)&ws[ic][k][o4 * 4];
                    fma2(acc0[o4 * 2 + 0], p0, wq.x);
                    fma2(acc0[o4 * 2 + 1], p0, wq.y);
                    fma2(acc1[o4 * 2 + 0], p1, wq.x);
                    fma2(acc1[o4 * 2 + 1], p1, wq.y);
                }
            }
        }
    }
    int x = tx0 + lx;
    int yA = ty0 + ly, yB = yA + 8;
    float thr = SOFT ? __ldg(thr_p) : 0.0f;
#pragma unroll
    for (int j = 0; j < 16; ++j) {
        float v0a, v0b, v1a, v1b;
        unpk2(v0a, v0b, acc0[j]);
        unpk2(v1a, v1b, acc1[j]);
        int oA = 2 * j, oB = 2 * j + 1;
        if (!SOFT) {
            v0a = fmaxf(v0a, 0.0f); v0b = fmaxf(v0b, 0.0f);
            v1a = fmaxf(v1a, 0.0f); v1b = fmaxf(v1b, 0.0f);
        }
        out[oA * NPIX + yA * W_IMG + x] = v0a;
        out[oB * NPIX + yA * W_IMG + x] = v0b;
        out[oA * NPIX + yB * W_IMG + x] = v1a;
        out[oB * NPIX + yB * W_IMG + x] = v1b;
        if (SOFT) {
            float m0a = fmaxf(fabsf(v0a) - thr, 0.0f);
            float m0b = fmaxf(fabsf(v0b) - thr, 0.0f);
            float m1a = fmaxf(fabsf(v1a) - thr, 0.0f);
            float m1b = fmaxf(fabsf(v1b) - thr, 0.0f);
            out2[oA * NPIX + yA * W_IMG + x] = (v0a > 0.0f) ? m0a : ((v0a < 0.0f) ? -m0a : 0.0f);
            out2[oB * NPIX + yA * W_IMG + x] = (v0b > 0.0f) ? m0b : ((v0b < 0.0f) ? -m0b : 0.0f);
            out2[oA * NPIX + yB * W_IMG + x] = (v1a > 0.0f) ? m1a : ((v1a < 0.0f) ? -m1a : 0.0f);
            out2[oB * NPIX + yB * W_IMG + x] = (v1b > 0.0f) ? m1b : ((v1b < 0.0f) ? -m1b : 0.0f);
        }
    }
}

// stage A: g_feat1 -> g_xforward (plain) + g_hs (soft-threshold)
__global__ void __launch_bounds__(128) k_conv32a(const float* __restrict__ w,
                                                 const float* __restrict__ thr_p) {
    conv32_tile<true>(g_feat1, g_xforward, g_hs, thr_p, w, blockIdx.x, threadIdx.x);
}

// stage B (merged): blocks [0,256): g_hs -> g_t1; [256,512): g_xforward -> g_t2
__global__ void __launch_bounds__(128) k_conv32b(const float* __restrict__ w) {
    int which = blockIdx.x >> 8;
    const float* in = which ? g_xforward : g_hs;
    float* out = which ? g_t2 : g_t1;
    conv32_tile<false>(in, out, nullptr, nullptr, w, blockIdx.x & 255, threadIdx.x);
}

// ---------------- conv 32->1 (3x3, SAME), merged pair ------------------------
__global__ void k_conv32to1(const float* __restrict__ w, float* __restrict__ outbase) {
    int sub = blockIdx.x >> 8;
    int tile = blockIdx.x & 255;
    const float* __restrict__ in = sub ? g_t2 : g_t1;
    float* __restrict__ out = outbase + sub * NPIX;
    __shared__ float ws[288];
    __shared__ float ins[8][18][18];
    int tid = threadIdx.x;
    for (int i = tid; i < 288; i += 256) ws[i] = w[i];
    int bx = tile & 15, by = tile >> 4;
    int tx0 = bx * 16, ty0 = by * 16;
    int lx = tid & 15, ly = tid >> 4;
    float acc = 0.0f;
    for (int cc = 0; cc < 4; ++cc) {
        __syncthreads();
        for (int i = tid; i < 8 * 18 * 18; i += 256) {
            int icc = i / 324;
            int rr = (i - icc * 324) / 18;
            int c2 = i - icc * 324 - rr * 18;
            int gy = ty0 - 1 + rr, gx2 = tx0 - 1 + c2;
            float v = 0.0f;
            if ((unsigned)gy < (unsigned)H_IMG && (unsigned)gx2 < (unsigned)W_IMG)
                v = in[(cc * 8 + icc) * NPIX + gy * W_IMG + gx2];
            ins[icc][rr][c2] = v;
        }
        __syncthreads();
#pragma unroll
        for (int icc = 0; icc < 8; ++icc) {
            int ic = cc * 8 + icc;
#pragma unroll
            for (int dy = 0; dy < 3; ++dy)
#pragma unroll
                for (int dxk = 0; dxk < 3; ++dxk)
                    acc = fmaf(ins[icc][ly + dy][lx + dxk], ws[ic * 9 + dy * 3 + dxk], acc);
        }
    }
    int pix = (ty0 + ly) * W_IMG + tx0 + lx;
    out[pix] = sub ? (acc - g_xinput[pix]) : acc;
}

// ---------------- launch ----------------
extern "C" void kernel_launch(void* const* d_in, const int* in_sizes, int n_in,
                              void* d_out, int out_size) {
    const float* x        = (const float*)d_in[0];
    const float* theta    = (const float*)d_in[1];
    const float* sinogram = (const float*)d_in[2];
    const float* lam      = (const float*)d_in[3];
    const float* thr      = (const float*)d_in[4];
    const float* w1f      = (const float*)d_in[5];
    const float* w2f      = (const float*)d_in[6];
    const float* w1b      = (const float*)d_in[7];
    const float* w2b      = (const float*)d_in[8];
    float* out = (float*)d_out;  // [0:65536) x_pred, [65536:131072) symloss

    k_fanfwd<<<2048, 256>>>(x, theta);          // 8 threads / ray
    k_filter<<<A_ANG, 256>>>(sinogram);         // fused closed-form ramp filter
    k_backproj<<<2048, 256>>>(theta, x, lam);   // 8 threads / pixel
    k_conv1f<<<256, 256>>>(w1f);
    k_conv32a<<<256, 128>>>(w2f, thr);
    k_conv32b<<<512, 128>>>(w1b);               // <-- ncu capture target next round
    k_conv32to1<<<512, 256>>>(w2b, out);
}

// round 6
// speedup vs baseline: 2.3352x; 1.0107x over previous
#include <cuda_runtime.h>
#include <math_constants.h>

#define H_IMG 256
#define W_IMG 256
#define A_ANG 64
#define DC_DET 1024
#define NSAMP 512
#define FEAT 32
#define NPIX (H_IMG * W_IMG)
#define IMG4_W 257

// ---------------- scratch (device globals: allocation-free) ----------------
__device__ float4 g_img4[IMG4_W * IMG4_W];  // packed bilinear quads, 1-px border
__device__ float g_sino[A_ANG * DC_DET];
__device__ float g_filt[A_ANG * DC_DET];
__device__ float g_xinput[NPIX];
__device__ float g_feat1[FEAT * NPIX];
__device__ float g_xforward[FEAT * NPIX];
__device__ float g_hs[FEAT * NPIX];
__device__ float g_t1[FEAT * NPIX];
__device__ float g_t2[FEAT * NPIX];

// ---------------- f32x2 packed-FMA helpers (Blackwell) ----------------
typedef unsigned long long u64t;
__device__ __forceinline__ u64t pk2(float x) {
    u64t r;
    asm("mov.b64 %0, {%1, %1};" : "=l"(r) : "f"(x));
    return r;
}
__device__ __forceinline__ void fma2(u64t& d, u64t a, u64t b) {
    asm("fma.rn.f32x2 %0, %1, %2, %0;" : "+l"(d) : "l"(a), "l"(b));
}
__device__ __forceinline__ void unpk2(float& lo, float& hi, u64t v) {
    asm("mov.b64 {%0, %1}, %2;" : "=f"(lo), "=f"(hi) : "l"(v));
}

// ---------------- prep: pack bilinear tap quads into float4 -----------------
__device__ __forceinline__ float img_tap(const float* __restrict__ img, int xi, int yi) {
    if ((unsigned)xi < (unsigned)W_IMG && (unsigned)yi < (unsigned)H_IMG)
        return __ldg(&img[yi * W_IMG + xi]);
    return 0.0f;
}

__global__ void k_prep(const float* __restrict__ img) {
    int i = blockIdx.x * 256 + threadIdx.x;
    if (i >= IMG4_W * IMG4_W) return;
    int yy = i / IMG4_W - 1;
    int xx = i - (yy + 1) * IMG4_W - 1;
    g_img4[i] = make_float4(img_tap(img, xx, yy), img_tap(img, xx + 1, yy),
                            img_tap(img, xx, yy + 1), img_tap(img, xx + 1, yy + 1));
}

// ---------------- fan-beam forward projection (8 threads / ray) -------------
// One LDG.128 per bilinear sample via g_img4.
__global__ void k_fanfwd(const float* __restrict__ theta) {
    int gid = blockIdx.x * blockDim.x + threadIdx.x;
    int ray = gid >> 3;
    int sub = gid & 7;
    int a = ray >> 10;
    int dc = ray & 1023;
    float th = theta[a];
    float c = cosf(th), s = sinf(th);
    float srcx = 500.0f * c, srcy = 500.0f * s;
    float u = ((float)dc - 511.5f) * 2.0f;
    float dx = -1000.0f * c - u * s;
    float dy = -1000.0f * s + u * c;
    float L = sqrtf(dx * dx + dy * dy);

    const float lo = -128.51f, hi = 128.51f;
    float tlo = 0.0f, thi = 1.0f;
    {
        if (fabsf(dx) > 1e-9f) {
            float ta = (lo - srcx) / dx, tb = (hi - srcx) / dx;
            tlo = fmaxf(tlo, fminf(ta, tb));
            thi = fminf(thi, fmaxf(ta, tb));
        } else if (srcx < lo || srcx > hi) { thi = -1.0f; }
        if (fabsf(dy) > 1e-9f) {
            float ta = (lo - srcy) / dy, tb = (hi - srcy) / dy;
            tlo = fmaxf(tlo, fminf(ta, tb));
            thi = fminf(thi, fmaxf(ta, tb));
        } else if (srcy < lo || srcy > hi) { thi = -1.0f; }
    }
    float acc = 0.0f;
    if (thi > tlo) {
        int kmin = (int)ceilf(tlo * (float)NSAMP - 0.5f) - 1;
        int kmax = (int)floorf(thi * (float)NSAMP - 0.5f) + 1;
        kmin = max(kmin, 0);
        kmax = min(kmax, NSAMP - 1);
        for (int k = kmin + sub; k <= kmax; k += 8) {
            float t = ((float)k + 0.5f) * (1.0f / (float)NSAMP);
            float px = fmaf(t, dx, srcx);
            float py = fmaf(t, dy, srcy);
            float cx = px + 127.5f, cy = py + 127.5f;
            float x0 = floorf(cx), y0 = floorf(cy);
            float fx = cx - x0, fy = cy - y0;
            int xi = (int)x0 + 1, yi = (int)y0 + 1;  // index into bordered img4
            if ((unsigned)xi < (unsigned)IMG4_W && (unsigned)yi < (unsigned)IMG4_W) {
                float4 v = __ldg(&g_img4[yi * IMG4_W + xi]);
                float vx0 = fmaf(fx, v.y - v.x, v.x);
                float vx1 = fmaf(fx, v.w - v.z, v.z);
                acc += fmaf(fy, vx1 - vx0, vx0);
            }
        }
    }
    acc += __shfl_xor_sync(0xFFFFFFFFu, acc, 1);
    acc += __shfl_xor_sync(0xFFFFFFFFu, acc, 2);
    acc += __shfl_xor_sync(0xFFFFFFFFu, acc, 4);
    if (sub == 0) g_sino[ray] = acc * (L * (1.0f / (float)NSAMP));
}

// ---------------- ramp filter, fused closed-form IR ----------------
// h[0]=0.5, h[even>0]=0, h[odd j] = -1/(2^21 sin^2(j*pi/2048)).
__global__ void __launch_bounds__(256) k_filter(const float* __restrict__ obs) {
    __shared__ float xs[DC_DET];
    __shared__ float hodd[1024];  // hodd[i] = h[2i+1]
    int a = blockIdx.x;
    int tid = threadIdx.x;
    for (int i = tid; i < 1024; i += 256) {
        float sh = sinf((float)(2 * i + 1) * 1.5339807878856412e-3f);  // pi/2048
        hodd[i] = -4.76837158203125e-7f / (sh * sh);                   // -1/2^21
    }
    for (int i = tid; i < DC_DET; i += 256) xs[i] = g_sino[a * DC_DET + i];
    __syncthreads();

    int t = tid;
    int b2t = 2 * t;
    float a0 = 0.f, a1 = 0.f, a2 = 0.f, a3 = 0.f;
#pragma unroll 4
    for (int kb = 0; kb < 512; kb += 4) {
        float4 X0 = *(float4*)&xs[2 * kb];
        float4 X1 = *(float4*)&xs[2 * kb + 4];
        int e0 = (b2t - kb - 4) & 1023;
        float2 w01 = *(float2*)&hodd[e0];
        float2 w23 = *(float2*)&hodd[(e0 + 2) & 1023];
        float2 w45 = *(float2*)&hodd[(e0 + 4) & 1023];
        float H0 = w01.x, H1 = w01.y, H2 = w23.x, H3 = w23.y, H4 = w45.x, H5 = w45.y;
        a0 = fmaf(H3, X0.y, a0); a1 = fmaf(H4, X0.x, a1);
        a2 = fmaf(H4, X0.y, a2); a3 = fmaf(H5, X0.x, a3);
        a0 = fmaf(H2, X0.w, a0); a1 = fmaf(H3, X0.z, a1);
        a2 = fmaf(H3, X0.w, a2); a3 = fmaf(H4, X0.z, a3);
        a0 = fmaf(H1, X1.y, a0); a1 = fmaf(H2, X1.x, a1);
        a2 = fmaf(H2, X1.y, a2); a3 = fmaf(H3, X1.x, a3);
        a0 = fmaf(H0, X1.w, a0); a1 = fmaf(H1, X1.z, a1);
        a2 = fmaf(H1, X1.w, a2); a3 = fmaf(H2, X1.z, a3);
    }
    int n = 4 * t;
    float4 xc = *(float4*)&xs[n];
    float4 o4 = *(const float4*)&obs[a * DC_DET + n];
    float4 res;
    res.x = fmaf(0.5f, xc.x, a0) - o4.x;
    res.y = fmaf(0.5f, xc.y, a1) - o4.y;
    res.z = fmaf(0.5f, xc.z, a2) - o4.z;
    res.w = fmaf(0.5f, xc.w, a3) - o4.w;
    *(float4*)&g_filt[a * DC_DET + n] = res;
}

// ---------------- backprojection + x_input (8 threads / pixel) --------------
__global__ void k_backproj(const float* __restrict__ theta, const float* __restrict__ x_in,
                           const float* __restrict__ lam_p) {
    __shared__ float cs[A_ANG], ss[A_ANG];
    int tid = threadIdx.x;
    if (tid < A_ANG) {
        float th = theta[tid];
        cs[tid] = cosf(th);
        ss[tid] = sinf(th);
    }
    __syncthreads();
    int pix = blockIdx.x * 32 + (tid >> 3);
    int oct = tid & 7;
    int py = pix >> 8, px = pix & 255;
    float gx = (float)px - 127.5f;
    float gy = (float)py - 127.5f;
    float accA = 0.0f, accB = 0.0f;
    int a0 = oct * 8;
#pragma unroll
    for (int j = 0; j < 8; j += 2) {
#pragma unroll
        for (int half = 0; half < 2; ++half) {
            int a = a0 + j + half;
            float c = cs[a], s = ss[a];
            float xr = gx * c + gy * s;
            float yr = -gx * s + gy * c;
            float invd = __fdividef(1.0f, 500.0f - xr);
            float uu = yr * 1000.0f * invd;
            float wgt = 250000.0f * invd * invd;
            float iu = uu * 0.5f + 511.5f;
            float i0f = floorf(iu);
            float fr = iu - i0f;
            int i0 = (int)i0f;
            const float* row = g_filt + a * DC_DET;
            float v0 = ((unsigned)i0 < (unsigned)DC_DET) ? __ldg(&row[i0]) : 0.0f;
            float v1 = ((unsigned)(i0 + 1) < (unsigned)DC_DET) ? __ldg(&row[i0 + 1]) : 0.0f;
            float term = wgt * fmaf(fr, v1 - v0, v0);
            if (half == 0) accA += term; else accB += term;
        }
    }
    float acc = accA + accB;
    acc += __shfl_xor_sync(0xFFFFFFFFu, acc, 1);
    acc += __shfl_xor_sync(0xFFFFFFFFu, acc, 2);
    acc += __shfl_xor_sync(0xFFFFFFFFu, acc, 4);
    if (oct == 0) {
        float lam = __ldg(lam_p);
        g_xinput[pix] = x_in[pix] - lam * acc * (float)(CUDART_PI / 64.0);
    }
}

// ---------------- conv 1->32 (3x3, SAME) + relu (2 threads / pixel) ---------
__global__ void k_conv1f(const float* __restrict__ w) {
    __shared__ float ws[9][32];
    int tid = threadIdx.x;
    for (int i = tid; i < 288; i += 256) {
        int k = i >> 5, oc = i & 31;
        ws[k][oc] = w[oc * 9 + k];
    }
    __syncthreads();
    int pix = blockIdx.x * 128 + (tid >> 1);
    int half = tid & 1;
    int py = pix >> 8, px = pix & 255;
    float pv[9];
#pragma unroll
    for (int dy = 0; dy < 3; ++dy)
#pragma unroll
        for (int dxk = 0; dxk < 3; ++dxk) {
            int yy = py - 1 + dy, xx = px - 1 + dxk;
            pv[dy * 3 + dxk] = ((unsigned)yy < (unsigned)H_IMG && (unsigned)xx < (unsigned)W_IMG)
                                   ? __ldg(&g_xinput[yy * W_IMG + xx]) : 0.0f;
        }
    float acc[16];
#pragma unroll
    for (int o = 0; o < 16; ++o) acc[o] = 0.0f;
    int ob = half * 16;
#pragma unroll
    for (int k = 0; k < 9; ++k) {
#pragma unroll
        for (int o4 = 0; o4 < 4; ++o4) {
            float4 wv = *(const float4*)&ws[k][ob + o4 * 4];
            acc[o4 * 4 + 0] = fmaf(pv[k], wv.x, acc[o4 * 4 + 0]);
            acc[o4 * 4 + 1] = fmaf(pv[k], wv.y, acc[o4 * 4 + 1]);
            acc[o4 * 4 + 2] = fmaf(pv[k], wv.z, acc[o4 * 4 + 2]);
            acc[o4 * 4 + 3] = fmaf(pv[k], wv.w, acc[o4 * 4 + 3]);
        }
    }
#pragma unroll
    for (int o = 0; o < 16; ++o)
        g_feat1[(ob + o) * NPIX + pix] = fmaxf(acc[o], 0.0f);
}

// ---------------- conv 32->32 core (f32x2 over oc pairs) --------------------
template <bool SOFT>
__device__ __forceinline__ void conv32_tile(const float* __restrict__ in,
                                            float* __restrict__ out,
                                            float* __restrict__ out2,
                                            const float* __restrict__ thr_p,
                                            const float* __restrict__ w,
                                            int tile, int tid) {
    __shared__ __align__(16) float ws[32][9][32];  // [ic][tap][oc]
    __shared__ float ins[8][18][18];
    for (int i = tid; i < 32 * 9 * 32; i += 128) {
        int oc = i / 288;
        int r = i - oc * 288;
        int ic = r / 9;
        int k = r - ic * 9;
        ws[ic][k][oc] = w[i];
    }
    int bx = tile & 15, by = tile >> 4;
    int tx0 = bx * 16, ty0 = by * 16;
    int lx = tid & 15, ly = tid >> 4;  // ly in [0,8)

    u64t acc0[16], acc1[16];
#pragma unroll
    for (int o = 0; o < 16; ++o) { acc0[o] = 0ull; acc1[o] = 0ull; }

    for (int cc = 0; cc < 4; ++cc) {
        __syncthreads();
        for (int i = tid; i < 8 * 18 * 18; i += 128) {
            int icc = i / 324;
            int rr = (i - icc * 324) / 18;
            int c2 = i - icc * 324 - rr * 18;
            int gy = ty0 - 1 + rr, gx2 = tx0 - 1 + c2;
            float v = 0.0f;
            if ((unsigned)gy < (unsigned)H_IMG && (unsigned)gx2 < (unsigned)W_IMG)
                v = in[(cc * 8 + icc) * NPIX + gy * W_IMG + gx2];
            ins[icc][rr][c2] = v;
        }
        __syncthreads();
#pragma unroll
        for (int icc = 0; icc < 8; ++icc) {
            int ic = cc * 8 + icc;
#pragma unroll
            for (int k = 0; k < 9; ++k) {
                int dy = k / 3, dxk = k - dy * 3;
                u64t p0 = pk2(ins[icc][ly + dy][lx + dxk]);
                u64t p1 = pk2(ins[icc][ly + 8 + dy][lx + dxk]);
#pragma unroll
                for (int o4 = 0; o4 < 8; ++o4) {
                    ulonglong2 wq = *(const ulonglong2*)&ws[ic][k][o4 * 4];
                    fma2(acc0[o4 * 2 + 0], p0, wq.x);
                    fma2(acc0[o4 * 2 + 1], p0, wq.y);
                    fma2(acc1[o4 * 2 + 0], p1, wq.x);
                    fma2(acc1[o4 * 2 + 1], p1, wq.y);
                }
            }
        }
    }
    int x = tx0 + lx;
    int yA = ty0 + ly, yB = yA + 8;
    float thr = SOFT ? __ldg(thr_p) : 0.0f;
#pragma unroll
    for (int j = 0; j < 16; ++j) {
        float v0a, v0b, v1a, v1b;
        unpk2(v0a, v0b, acc0[j]);
        unpk2(v1a, v1b, acc1[j]);
        int oA = 2 * j, oB = 2 * j + 1;
        if (!SOFT) {
            v0a = fmaxf(v0a, 0.0f); v0b = fmaxf(v0b, 0.0f);
            v1a = fmaxf(v1a, 0.0f); v1b = fmaxf(v1b, 0.0f);
        }
        out[oA * NPIX + yA * W_IMG + x] = v0a;
        out[oB * NPIX + yA * W_IMG + x] = v0b;
        out[oA * NPIX + yB * W_IMG + x] = v1a;
        out[oB * NPIX + yB * W_IMG + x] = v1b;
        if (SOFT) {
            float m0a = fmaxf(fabsf(v0a) - thr, 0.0f);
            float m0b = fmaxf(fabsf(v0b) - thr, 0.0f);
            float m1a = fmaxf(fabsf(v1a) - thr, 0.0f);
            float m1b = fmaxf(fabsf(v1b) - thr, 0.0f);
            out2[oA * NPIX + yA * W_IMG + x] = (v0a > 0.0f) ? m0a : ((v0a < 0.0f) ? -m0a : 0.0f);
            out2[oB * NPIX + yA * W_IMG + x] = (v0b > 0.0f) ? m0b : ((v0b < 0.0f) ? -m0b : 0.0f);
            out2[oA * NPIX + yB * W_IMG + x] = (v1a > 0.0f) ? m1a : ((v1a < 0.0f) ? -m1a : 0.0f);
            out2[oB * NPIX + yB * W_IMG + x] = (v1b > 0.0f) ? m1b : ((v1b < 0.0f) ? -m1b : 0.0f);
        }
    }
}

// stage A: g_feat1 -> g_xforward (plain) + g_hs (soft-threshold)
__global__ void __launch_bounds__(128) k_conv32a(const float* __restrict__ w,
                                                 const float* __restrict__ thr_p) {
    conv32_tile<true>(g_feat1, g_xforward, g_hs, thr_p, w, blockIdx.x, threadIdx.x);
}

// stage B (merged): blocks [0,256): g_hs -> g_t1; [256,512): g_xforward -> g_t2
__global__ void __launch_bounds__(128) k_conv32b(const float* __restrict__ w) {
    int which = blockIdx.x >> 8;
    const float* in = which ? g_xforward : g_hs;
    float* out = which ? g_t2 : g_t1;
    conv32_tile<false>(in, out, nullptr, nullptr, w, blockIdx.x & 255, threadIdx.x);
}

// ---------------- conv 32->1 (3x3, SAME), merged pair ------------------------
__global__ void k_conv32to1(const float* __restrict__ w, float* __restrict__ outbase) {
    int sub = blockIdx.x >> 8;
    int tile = blockIdx.x & 255;
    const float* __restrict__ in = sub ? g_t2 : g_t1;
    float* __restrict__ out = outbase + sub * NPIX;
    __shared__ float ws[288];
    __shared__ float ins[8][18][18];
    int tid = threadIdx.x;
    for (int i = tid; i < 288; i += 256) ws[i] = w[i];
    int bx = tile & 15, by = tile >> 4;
    int tx0 = bx * 16, ty0 = by * 16;
    int lx = tid & 15, ly = tid >> 4;
    float acc = 0.0f;
    for (int cc = 0; cc < 4; ++cc) {
        __syncthreads();
        for (int i = tid; i < 8 * 18 * 18; i += 256) {
            int icc = i / 324;
            int rr = (i - icc * 324) / 18;
            int c2 = i - icc * 324 - rr * 18;
            int gy = ty0 - 1 + rr, gx2 = tx0 - 1 + c2;
            float v = 0.0f;
            if ((unsigned)gy < (unsigned)H_IMG && (unsigned)gx2 < (unsigned)W_IMG)
                v = in[(cc * 8 + icc) * NPIX + gy * W_IMG + gx2];
            ins[icc][rr][c2] = v;
        }
        __syncthreads();
#pragma unroll
        for (int icc = 0; icc < 8; ++icc) {
            int ic = cc * 8 + icc;
#pragma unroll
            for (int dy = 0; dy < 3; ++dy)
#pragma unroll
                for (int dxk = 0; dxk < 3; ++dxk)
                    acc = fmaf(ins[icc][ly + dy][lx + dxk], ws[ic * 9 + dy * 3 + dxk], acc);
        }
    }
    int pix = (ty0 + ly) * W_IMG + tx0 + lx;
    out[pix] = sub ? (acc - g_xinput[pix]) : acc;
}

// ---------------- launch ----------------
extern "C" void kernel_launch(void* const* d_in, const int* in_sizes, int n_in,
                              void* d_out, int out_size) {
    const float* x        = (const float*)d_in[0];
    const float* theta    = (const float*)d_in[1];
    const float* sinogram = (const float*)d_in[2];
    const float* lam      = (const float*)d_in[3];
    const float* thr      = (const float*)d_in[4];
    const float* w1f      = (const float*)d_in[5];
    const float* w2f      = (const float*)d_in[6];
    const float* w1b      = (const float*)d_in[7];
    const float* w2b      = (const float*)d_in[8];
    float* out = (float*)d_out;  // [0:65536) x_pred, [65536:131072) symloss

    k_prep<<<(IMG4_W * IMG4_W + 255) / 256, 256>>>(x);
    k_fanfwd<<<2048, 256>>>(theta);             // 1 LDG.128 / bilinear sample
    k_filter<<<A_ANG, 256>>>(sinogram);
    k_backproj<<<2048, 256>>>(theta, x, lam);
    k_conv1f<<<512, 256>>>(w1f);                // 2 threads / pixel
    k_conv32a<<<256, 128>>>(w2f, thr);
    k_conv32b<<<512, 128>>>(w1b);
    k_conv32to1<<<512, 256>>>(w2b, out);
}

// round 7
// speedup vs baseline: 2.6894x; 1.1516x over previous
#include <cuda_runtime.h>
#include <math_constants.h>

#define H_IMG 256
#define W_IMG 256
#define A_ANG 64
#define DC_DET 1024
#define NSAMP 512
#define FEAT 32
#define NPIX (H_IMG * W_IMG)
#define IMG4_W 257
#define NRAY (A_ANG * DC_DET)

// ---------------- scratch (device globals: allocation-free) ----------------
__device__ float4 g_img4[IMG4_W * IMG4_W];  // packed bilinear quads, 1-px border
__device__ float4 g_rayA[NRAY];             // srcx, srcy, dx, dy
__device__ float4 g_rayB[NRAY];             // kmin(bits), kmax(bits), scale, -
__device__ float g_sino[NRAY];
__device__ float g_filt[NRAY];
__device__ float g_xinput[NPIX];
__device__ float g_feat1[FEAT * NPIX];
__device__ float g_xforward[FEAT * NPIX];
__device__ float g_hs[FEAT * NPIX];
__device__ float g_t1[FEAT * NPIX];
__device__ float g_t2[FEAT * NPIX];

// ---------------- f32x2 packed-FMA helpers (Blackwell) ----------------
typedef unsigned long long u64t;
__device__ __forceinline__ u64t pk2(float x) {
    u64t r;
    asm("mov.b64 %0, {%1, %1};" : "=l"(r) : "f"(x));
    return r;
}
__device__ __forceinline__ void fma2(u64t& d, u64t a, u64t b) {
    asm("fma.rn.f32x2 %0, %1, %2, %0;" : "+l"(d) : "l"(a), "l"(b));
}
__device__ __forceinline__ void unpk2(float& lo, float& hi, u64t v) {
    asm("mov.b64 {%0, %1}, %2;" : "=f"(lo), "=f"(hi) : "l"(v));
}

// ---------------- prep (img4 packing) + per-ray geometry, one launch --------
__device__ __forceinline__ float img_tap(const float* __restrict__ img, int xi, int yi) {
    if ((unsigned)xi < (unsigned)W_IMG && (unsigned)yi < (unsigned)H_IMG)
        return __ldg(&img[yi * W_IMG + xi]);
    return 0.0f;
}

#define PREP_BLOCKS 259   // ceil(257*257/256)
#define GEOM_BLOCKS 256   // 65536/256

__global__ void k_prepgeom(const float* __restrict__ img, const float* __restrict__ theta) {
    if (blockIdx.x < PREP_BLOCKS) {
        int i = blockIdx.x * 256 + threadIdx.x;
        if (i >= IMG4_W * IMG4_W) return;
        int yy = i / IMG4_W - 1;
        int xx = i - (yy + 1) * IMG4_W - 1;
        g_img4[i] = make_float4(img_tap(img, xx, yy), img_tap(img, xx + 1, yy),
                                img_tap(img, xx, yy + 1), img_tap(img, xx + 1, yy + 1));
        return;
    }
    int ray = (blockIdx.x - PREP_BLOCKS) * 256 + threadIdx.x;
    int a = ray >> 10;
    int dc = ray & 1023;
    float th = theta[a];
    float c = cosf(th), s = sinf(th);
    float srcx = 500.0f * c, srcy = 500.0f * s;
    float u = ((float)dc - 511.5f) * 2.0f;
    float dx = -1000.0f * c - u * s;
    float dy = -1000.0f * s + u * c;
    float L = sqrtf(dx * dx + dy * dy);

    const float lo = -128.51f, hi = 128.51f;
    float tlo = 0.0f, thi = 1.0f;
    if (fabsf(dx) > 1e-9f) {
        float ta = (lo - srcx) / dx, tb = (hi - srcx) / dx;
        tlo = fmaxf(tlo, fminf(ta, tb));
        thi = fminf(thi, fmaxf(ta, tb));
    } else if (srcx < lo || srcx > hi) { thi = -1.0f; }
    if (fabsf(dy) > 1e-9f) {
        float ta = (lo - srcy) / dy, tb = (hi - srcy) / dy;
        tlo = fmaxf(tlo, fminf(ta, tb));
        thi = fminf(thi, fmaxf(ta, tb));
    } else if (srcy < lo || srcy > hi) { thi = -1.0f; }

    int kmin = 1, kmax = 0;  // empty
    if (thi > tlo) {
        kmin = max((int)ceilf(tlo * (float)NSAMP - 0.5f) - 1, 0);
        kmax = min((int)floorf(thi * (float)NSAMP - 0.5f) + 1, NSAMP - 1);
    }
    g_rayA[ray] = make_float4(srcx, srcy, dx, dy);
    g_rayB[ray] = make_float4(__int_as_float(kmin), __int_as_float(kmax),
                              L * (1.0f / (float)NSAMP), 0.0f);
}

// ---------------- fan-beam forward projection (8 threads / ray) -------------
__global__ void k_fanfwd() {
    int gid = blockIdx.x * blockDim.x + threadIdx.x;
    int ray = gid >> 3;
    int sub = gid & 7;
    float4 A = __ldg(&g_rayA[ray]);
    float4 B = __ldg(&g_rayB[ray]);
    int kmin = __float_as_int(B.x);
    int kmax = __float_as_int(B.y);
    float acc = 0.0f;
    for (int k = kmin + sub; k <= kmax; k += 8) {
        float t = ((float)k + 0.5f) * (1.0f / (float)NSAMP);
        float cx = fmaf(t, A.z, A.x) + 127.5f;
        float cy = fmaf(t, A.w, A.y) + 127.5f;
        float x0 = floorf(cx), y0 = floorf(cy);
        float fx = cx - x0, fy = cy - y0;
        int xi = (int)x0 + 1, yi = (int)y0 + 1;
        if ((unsigned)xi < (unsigned)IMG4_W && (unsigned)yi < (unsigned)IMG4_W) {
            float4 v = __ldg(&g_img4[yi * IMG4_W + xi]);
            float vx0 = fmaf(fx, v.y - v.x, v.x);
            float vx1 = fmaf(fx, v.w - v.z, v.z);
            acc += fmaf(fy, vx1 - vx0, vx0);
        }
    }
    acc += __shfl_xor_sync(0xFFFFFFFFu, acc, 1);
    acc += __shfl_xor_sync(0xFFFFFFFFu, acc, 2);
    acc += __shfl_xor_sync(0xFFFFFFFFu, acc, 4);
    if (sub == 0) g_sino[ray] = acc * B.z;
}

// ---------------- ramp filter, fused closed-form IR ----------------
// h[0]=0.5, h[even>0]=0, h[odd j] = -1/(2^21 sin^2(j*pi/2048)).
__global__ void __launch_bounds__(256) k_filter(const float* __restrict__ obs) {
    __shared__ float xs[DC_DET];
    __shared__ float hodd[1024];
    int a = blockIdx.x;
    int tid = threadIdx.x;
    for (int i = tid; i < 1024; i += 256) {
        float sh = sinf((float)(2 * i + 1) * 1.5339807878856412e-3f);  // pi/2048
        hodd[i] = -4.76837158203125e-7f / (sh * sh);                   // -1/2^21
    }
    for (int i = tid; i < DC_DET; i += 256) xs[i] = g_sino[a * DC_DET + i];
    __syncthreads();

    int t = tid;
    int b2t = 2 * t;
    float a0 = 0.f, a1 = 0.f, a2 = 0.f, a3 = 0.f;
#pragma unroll 4
    for (int kb = 0; kb < 512; kb += 4) {
        float4 X0 = *(float4*)&xs[2 * kb];
        float4 X1 = *(float4*)&xs[2 * kb + 4];
        int e0 = (b2t - kb - 4) & 1023;
        float2 w01 = *(float2*)&hodd[e0];
        float2 w23 = *(float2*)&hodd[(e0 + 2) & 1023];
        float2 w45 = *(float2*)&hodd[(e0 + 4) & 1023];
        float H0 = w01.x, H1 = w01.y, H2 = w23.x, H3 = w23.y, H4 = w45.x, H5 = w45.y;
        a0 = fmaf(H3, X0.y, a0); a1 = fmaf(H4, X0.x, a1);
        a2 = fmaf(H4, X0.y, a2); a3 = fmaf(H5, X0.x, a3);
        a0 = fmaf(H2, X0.w, a0); a1 = fmaf(H3, X0.z, a1);
        a2 = fmaf(H3, X0.w, a2); a3 = fmaf(H4, X0.z, a3);
        a0 = fmaf(H1, X1.y, a0); a1 = fmaf(H2, X1.x, a1);
        a2 = fmaf(H2, X1.y, a2); a3 = fmaf(H3, X1.x, a3);
        a0 = fmaf(H0, X1.w, a0); a1 = fmaf(H1, X1.z, a1);
        a2 = fmaf(H1, X1.w, a2); a3 = fmaf(H2, X1.z, a3);
    }
    int n = 4 * t;
    float4 xc = *(float4*)&xs[n];
    float4 o4 = *(const float4*)&obs[a * DC_DET + n];
    float4 res;
    res.x = fmaf(0.5f, xc.x, a0) - o4.x;
    res.y = fmaf(0.5f, xc.y, a1) - o4.y;
    res.z = fmaf(0.5f, xc.z, a2) - o4.z;
    res.w = fmaf(0.5f, xc.w, a3) - o4.w;
    *(float4*)&g_filt[a * DC_DET + n] = res;
}

// ---------------- backprojection + x_input (coalesced; warp = angle group) --
// Block: 256 threads = 8 warps. Lane = consecutive pixel (coalesced detector
// reads); warp w handles angles [8w, 8w+8). Cross-warp reduce via smem.
__global__ void __launch_bounds__(256) k_backproj(const float* __restrict__ theta,
                                                  const float* __restrict__ x_in,
                                                  const float* __restrict__ lam_p) {
    __shared__ float cs[A_ANG], ss[A_ANG];
    __shared__ float partial[8][33];
    int tid = threadIdx.x;
    if (tid < A_ANG) {
        float th = theta[tid];
        cs[tid] = cosf(th);
        ss[tid] = sinf(th);
    }
    __syncthreads();
    int lane = tid & 31;
    int wrp = tid >> 5;
    int pix = blockIdx.x * 32 + lane;
    int py = pix >> 8, px = pix & 255;
    float gx = (float)px - 127.5f;
    float gy = (float)py - 127.5f;
    float accA = 0.0f, accB = 0.0f;
    int a0 = wrp * 8;
#pragma unroll
    for (int j = 0; j < 8; j += 2) {
#pragma unroll
        for (int half = 0; half < 2; ++half) {
            int a = a0 + j + half;
            float c = cs[a], s = ss[a];
            float xr = gx * c + gy * s;
            float yr = -gx * s + gy * c;
            float invd = __fdividef(1.0f, 500.0f - xr);
            float uu = yr * 1000.0f * invd;
            float wgt = 250000.0f * invd * invd;
            float iu = uu * 0.5f + 511.5f;
            float i0f = floorf(iu);
            float fr = iu - i0f;
            int i0 = (int)i0f;
            const float* row = g_filt + a * DC_DET;
            float v0 = ((unsigned)i0 < (unsigned)DC_DET) ? __ldg(&row[i0]) : 0.0f;
            float v1 = ((unsigned)(i0 + 1) < (unsigned)DC_DET) ? __ldg(&row[i0 + 1]) : 0.0f;
            float term = wgt * fmaf(fr, v1 - v0, v0);
            if (half == 0) accA += term; else accB += term;
        }
    }
    partial[wrp][lane] = accA + accB;
    __syncthreads();
    if (wrp == 0) {
        float acc = partial[0][lane] + partial[1][lane] + partial[2][lane] + partial[3][lane] +
                    partial[4][lane] + partial[5][lane] + partial[6][lane] + partial[7][lane];
        float lam = __ldg(lam_p);
        g_xinput[pix] = x_in[pix] - lam * acc * (float)(CUDART_PI / 64.0);
    }
}

// ---------------- conv 1->32 (3x3, SAME) + relu (2 threads / pixel) ---------
__global__ void k_conv1f(const float* __restrict__ w) {
    __shared__ float ws[9][32];
    int tid = threadIdx.x;
    for (int i = tid; i < 288; i += 256) {
        int k = i >> 5, oc = i & 31;
        ws[k][oc] = w[oc * 9 + k];
    }
    __syncthreads();
    int pix = blockIdx.x * 128 + (tid >> 1);
    int half = tid & 1;
    int py = pix >> 8, px = pix & 255;
    float pv[9];
#pragma unroll
    for (int dy = 0; dy < 3; ++dy)
#pragma unroll
        for (int dxk = 0; dxk < 3; ++dxk) {
            int yy = py - 1 + dy, xx = px - 1 + dxk;
            pv[dy * 3 + dxk] = ((unsigned)yy < (unsigned)H_IMG && (unsigned)xx < (unsigned)W_IMG)
                                   ? __ldg(&g_xinput[yy * W_IMG + xx]) : 0.0f;
        }
    float acc[16];
#pragma unroll
    for (int o = 0; o < 16; ++o) acc[o] = 0.0f;
    int ob = half * 16;
#pragma unroll
    for (int k = 0; k < 9; ++k) {
#pragma unroll
        for (int o4 = 0; o4 < 4; ++o4) {
            float4 wv = *(const float4*)&ws[k][ob + o4 * 4];
            acc[o4 * 4 + 0] = fmaf(pv[k], wv.x, acc[o4 * 4 + 0]);
            acc[o4 * 4 + 1] = fmaf(pv[k], wv.y, acc[o4 * 4 + 1]);
            acc[o4 * 4 + 2] = fmaf(pv[k], wv.z, acc[o4 * 4 + 2]);
            acc[o4 * 4 + 3] = fmaf(pv[k], wv.w, acc[o4 * 4 + 3]);
        }
    }
#pragma unroll
    for (int o = 0; o < 16; ++o)
        g_feat1[(ob + o) * NPIX + pix] = fmaxf(acc[o], 0.0f);
}

// ---------------- conv 32->32 core, oc-split (16 oc per block) --------------
// f32x2 packed over oc pairs. Block = 128 threads, 16x16 tile, 2 px/thread.
template <bool SOFT>
__device__ __forceinline__ void conv32_tile(const float* __restrict__ in,
                                            float* __restrict__ out,
                                            float* __restrict__ out2,
                                            const float* __restrict__ thr_p,
                                            const float* __restrict__ w,
                                            int tile, int half, int tid) {
    __shared__ __align__(16) float ws[32][9][16];  // [ic][tap][oc_local]
    __shared__ float ins[8][18][18];
    int ocbase = half * 16;
    for (int i = tid; i < 32 * 9 * 16; i += 128) {
        int ocl = i / 288;             // 0..15
        int r = i - ocl * 288;         // ic*9 + k
        int ic = r / 9;
        int k = r - ic * 9;
        ws[ic][k][ocl] = w[(ocbase + ocl) * 288 + r];
    }
    int bx = tile & 15, by = tile >> 4;
    int tx0 = bx * 16, ty0 = by * 16;
    int lx = tid & 15, ly = tid >> 4;  // ly in [0,8)

    u64t acc0[8], acc1[8];
#pragma unroll
    for (int o = 0; o < 8; ++o) { acc0[o] = 0ull; acc1[o] = 0ull; }

    for (int cc = 0; cc < 4; ++cc) {
        __syncthreads();
        for (int i = tid; i < 8 * 18 * 18; i += 128) {
            int icc = i / 324;
            int rr = (i - icc * 324) / 18;
            int c2 = i - icc * 324 - rr * 18;
            int gy = ty0 - 1 + rr, gx2 = tx0 - 1 + c2;
            float v = 0.0f;
            if ((unsigned)gy < (unsigned)H_IMG && (unsigned)gx2 < (unsigned)W_IMG)
                v = in[(cc * 8 + icc) * NPIX + gy * W_IMG + gx2];
            ins[icc][rr][c2] = v;
        }
        __syncthreads();
#pragma unroll
        for (int icc = 0; icc < 8; ++icc) {
            int ic = cc * 8 + icc;
#pragma unroll
            for (int k = 0; k < 9; ++k) {
                int dy = k / 3, dxk = k - dy * 3;
                u64t p0 = pk2(ins[icc][ly + dy][lx + dxk]);
                u64t p1 = pk2(ins[icc][ly + 8 + dy][lx + dxk]);
#pragma unroll
                for (int o4 = 0; o4 < 4; ++o4) {
                    ulonglong2 wq = *(const ulonglong2*)&ws[ic][k][o4 * 4];
                    fma2(acc0[o4 * 2 + 0], p0, wq.x);
                    fma2(acc0[o4 * 2 + 1], p0, wq.y);
                    fma2(acc1[o4 * 2 + 0], p1, wq.x);
                    fma2(acc1[o4 * 2 + 1], p1, wq.y);
                }
            }
        }
    }
    int x = tx0 + lx;
    int yA = ty0 + ly, yB = yA + 8;
    float thr = SOFT ? __ldg(thr_p) : 0.0f;
#pragma unroll
    for (int j = 0; j < 8; ++j) {
        float v0a, v0b, v1a, v1b;
        unpk2(v0a, v0b, acc0[j]);
        unpk2(v1a, v1b, acc1[j]);
        int oA = ocbase + 2 * j, oB = oA + 1;
        if (!SOFT) {
            v0a = fmaxf(v0a, 0.0f); v0b = fmaxf(v0b, 0.0f);
            v1a = fmaxf(v1a, 0.0f); v1b = fmaxf(v1b, 0.0f);
        }
        out[oA * NPIX + yA * W_IMG + x] = v0a;
        out[oB * NPIX + yA * W_IMG + x] = v0b;
        out[oA * NPIX + yB * W_IMG + x] = v1a;
        out[oB * NPIX + yB * W_IMG + x] = v1b;
        if (SOFT) {
            float m0a = fmaxf(fabsf(v0a) - thr, 0.0f);
            float m0b = fmaxf(fabsf(v0b) - thr, 0.0f);
            float m1a = fmaxf(fabsf(v1a) - thr, 0.0f);
            float m1b = fmaxf(fabsf(v1b) - thr, 0.0f);
            out2[oA * NPIX + yA * W_IMG + x] = (v0a > 0.0f) ? m0a : ((v0a < 0.0f) ? -m0a : 0.0f);
            out2[oB * NPIX + yA * W_IMG + x] = (v0b > 0.0f) ? m0b : ((v0b < 0.0f) ? -m0b : 0.0f);
            out2[oA * NPIX + yB * W_IMG + x] = (v1a > 0.0f) ? m1a : ((v1a < 0.0f) ? -m1a : 0.0f);
            out2[oB * NPIX + yB * W_IMG + x] = (v1b > 0.0f) ? m1b : ((v1b < 0.0f) ? -m1b : 0.0f);
        }
    }
}

// stage A (512 blocks): g_feat1 -> g_xforward + g_hs ; half = blockIdx>>8
__global__ void __launch_bounds__(128) k_conv32a(const float* __restrict__ w,
                                                 const float* __restrict__ thr_p) {
    conv32_tile<true>(g_feat1, g_xforward, g_hs, thr_p, w,
                      blockIdx.x & 255, blockIdx.x >> 8, threadIdx.x);
}

// stage B (1024 blocks): which = blockIdx>>9, half = (blockIdx>>8)&1
__global__ void __launch_bounds__(128) k_conv32b(const float* __restrict__ w) {
    int which = blockIdx.x >> 9;
    const float* in = which ? g_xforward : g_hs;
    float* out = which ? g_t2 : g_t1;
    conv32_tile<false>(in, out, nullptr, nullptr, w,
                       blockIdx.x & 255, (blockIdx.x >> 8) & 1, threadIdx.x);
}

// ---------------- conv 32->1 (3x3, SAME), merged pair ------------------------
__global__ void k_conv32to1(const float* __restrict__ w, float* __restrict__ outbase) {
    int sub = blockIdx.x >> 8;
    int tile = blockIdx.x & 255;
    const float* __restrict__ in = sub ? g_t2 : g_t1;
    float* __restrict__ out = outbase + sub * NPIX;
    __shared__ float ws[288];
    __shared__ float ins[8][18][18];
    int tid = threadIdx.x;
    for (int i = tid; i < 288; i += 256) ws[i] = w[i];
    int bx = tile & 15, by = tile >> 4;
    int tx0 = bx * 16, ty0 = by * 16;
    int lx = tid & 15, ly = tid >> 4;
    float acc = 0.0f;
    for (int cc = 0; cc < 4; ++cc) {
        __syncthreads();
        for (int i = tid; i < 8 * 18 * 18; i += 256) {
            int icc = i / 324;
            int rr = (i - icc * 324) / 18;
            int c2 = i - icc * 324 - rr * 18;
            int gy = ty0 - 1 + rr, gx2 = tx0 - 1 + c2;
            float v = 0.0f;
            if ((unsigned)gy < (unsigned)H_IMG && (unsigned)gx2 < (unsigned)W_IMG)
                v = in[(cc * 8 + icc) * NPIX + gy * W_IMG + gx2];
            ins[icc][rr][c2] = v;
        }
        __syncthreads();
#pragma unroll
        for (int icc = 0; icc < 8; ++icc) {
            int ic = cc * 8 + icc;
#pragma unroll
            for (int dy = 0; dy < 3; ++dy)
#pragma unroll
                for (int dxk = 0; dxk < 3; ++dxk)
                    acc = fmaf(ins[icc][ly + dy][lx + dxk], ws[ic * 9 + dy * 3 + dxk], acc);
        }
    }
    int pix = (ty0 + ly) * W_IMG + tx0 + lx;
    out[pix] = sub ? (acc - g_xinput[pix]) : acc;
}

// ---------------- launch ----------------
extern "C" void kernel_launch(void* const* d_in, const int* in_sizes, int n_in,
                              void* d_out, int out_size) {
    const float* x        = (const float*)d_in[0];
    const float* theta    = (const float*)d_in[1];
    const float* sinogram = (const float*)d_in[2];
    const float* lam      = (const float*)d_in[3];
    const float* thr      = (const float*)d_in[4];
    const float* w1f      = (const float*)d_in[5];
    const float* w2f      = (const float*)d_in[6];
    const float* w1b      = (const float*)d_in[7];
    const float* w2b      = (const float*)d_in[8];
    float* out = (float*)d_out;  // [0:65536) x_pred, [65536:131072) symloss

    k_prepgeom<<<PREP_BLOCKS + GEOM_BLOCKS, 256>>>(x, theta);
    k_fanfwd<<<2048, 256>>>();                  // setup hoisted to k_prepgeom
    k_filter<<<A_ANG, 256>>>(sinogram);
    k_backproj<<<2048, 256>>>(theta, x, lam);   // coalesced detector reads
    k_conv1f<<<512, 256>>>(w1f);
    k_conv32a<<<512, 128>>>(w2f, thr);          // oc-split
    k_conv32b<<<1024, 128>>>(w1b);              // oc-split
    k_conv32to1<<<512, 256>>>(w2b, out);
}